// round 1
// baseline (speedup 1.0000x reference)
#include <cuda_runtime.h>
#include <math.h>
#include <float.h>

// Problem constants (shapes fixed by the dataset generator)
#define NNODES 50000
#define FIN    128
#define DDIM   250
#define DPAD   256
#define HDIM   256
#define EMAXT  850000   // E + N self loops

// ---------------- scratch (device globals; no runtime allocation) ----------
__device__ float g_xl [NNODES * DPAD];
__device__ float g_xr [NNODES * DPAD];
__device__ float g_h  [NNODES * DPAD];
__device__ float g_emb[NNODES * DPAD];
__device__ float g_e  [EMAXT];
__device__ float g_m  [NNODES];
__device__ float g_s  [NNODES];

// ---------------- init kernels ---------------------------------------------
__global__ void init_nodes_kernel(float* m, float* s, int n) {
    int i = blockIdx.x * blockDim.x + threadIdx.x;
    if (i < n) { m[i] = -FLT_MAX; s[i] = 0.f; }
}

__global__ void zero_kernel(float* p, int n) {
    int i = blockIdx.x * blockDim.x + threadIdx.x;
    int stride = gridDim.x * blockDim.x;
    for (; i < n; i += stride) p[i] = 0.f;
}

// ---------------- tiled fp32 GEMM: C[M,N] = A[M,K]*B[K,N] (+bias) ----------
#define BM 64
#define BN 64
#define BK 16
__global__ void gemm_bias_kernel(const float* __restrict__ A, int lda,
                                 const float* __restrict__ B, int ldb,
                                 const float* __restrict__ bias,
                                 float* __restrict__ C, int ldc,
                                 int M, int K, int N) {
    __shared__ float As[BK][BM + 1];
    __shared__ float Bs[BK][BN + 1];
    int tid = threadIdx.x;                 // 0..255
    int block_row = blockIdx.y * BM;
    int block_col = blockIdx.x * BN;
    int tr = (tid / 16) * 4;
    int tc = (tid % 16) * 4;
    float acc[4][4] = {};

    for (int k0 = 0; k0 < K; k0 += BK) {
        #pragma unroll
        for (int i = 0; i < 4; i++) {      // A tile: BM x BK
            int idx = tid + i * 256;
            int m = idx / BK, k = idx % BK;
            int gm = block_row + m, gk = k0 + k;
            float v = 0.f;
            if (gm < M && gk < K) v = A[(size_t)gm * lda + gk];
            As[k][m] = v;
        }
        #pragma unroll
        for (int i = 0; i < 4; i++) {      // B tile: BK x BN
            int idx = tid + i * 256;
            int k = idx / BN, n = idx % BN;
            int gk = k0 + k, gn = block_col + n;
            float v = 0.f;
            if (gk < K && gn < N) v = B[(size_t)gk * ldb + gn];
            Bs[k][n] = v;
        }
        __syncthreads();
        #pragma unroll
        for (int k = 0; k < BK; k++) {
            float a[4], b[4];
            #pragma unroll
            for (int i = 0; i < 4; i++) a[i] = As[k][tr + i];
            #pragma unroll
            for (int j = 0; j < 4; j++) b[j] = Bs[k][tc + j];
            #pragma unroll
            for (int i = 0; i < 4; i++)
                #pragma unroll
                for (int j = 0; j < 4; j++)
                    acc[i][j] += a[i] * b[j];
        }
        __syncthreads();
    }

    #pragma unroll
    for (int i = 0; i < 4; i++) {
        int gm = block_row + tr + i;
        if (gm >= M) continue;
        #pragma unroll
        for (int j = 0; j < 4; j++) {
            int gn = block_col + tc + j;
            if (gn >= N) continue;
            float v = acc[i][j];
            if (bias) v += bias[gn];
            C[(size_t)gm * ldc + gn] = v;
        }
    }
}

// ---------------- float atomic max (sign-split trick) ----------------------
__device__ __forceinline__ void atomicMaxFloat(float* addr, float v) {
    if (v >= 0.f) atomicMax((int*)addr, __float_as_int(v));
    else          atomicMin((unsigned int*)addr, __float_as_uint(v));
}

__device__ __forceinline__ void edge_src_dst(const int* __restrict__ ei,
                                             int k, int E, int& src, int& dst) {
    if (k < E) { src = ei[k]; dst = ei[E + k]; }
    else       { src = k - E; dst = k - E; }
}

// ---------------- edge pass 1: e = att . leaky_relu(xl[src]+xr[dst]) -------
__global__ void edge_e_kernel(const float* __restrict__ xl,
                              const float* __restrict__ xr,
                              const float* __restrict__ att,
                              const int*   __restrict__ ei,
                              float* __restrict__ ebuf,
                              float* __restrict__ m,
                              int E, int Etot) {
    int k = (blockIdx.x * blockDim.x + threadIdx.x) >> 5;
    if (k >= Etot) return;
    int lane = threadIdx.x & 31;
    int src, dst; edge_src_dst(ei, k, E, src, dst);
    const float* xls = xl + (size_t)src * DPAD;
    const float* xrd = xr + (size_t)dst * DPAD;
    float partial = 0.f;
    #pragma unroll
    for (int d = lane; d < DDIM; d += 32) {
        float v = xls[d] + xrd[d];
        v = (v > 0.f) ? v : 0.2f * v;
        partial += att[d] * v;
    }
    #pragma unroll
    for (int off = 16; off; off >>= 1)
        partial += __shfl_down_sync(0xffffffffu, partial, off);
    if (lane == 0) {
        ebuf[k] = partial;
        atomicMaxFloat(&m[dst], partial);
    }
}

// ---------------- edge pass 2: accumulate exp-weighted messages ------------
__global__ void edge_agg_kernel(const float* __restrict__ xl,
                                const float* __restrict__ ebuf,
                                const float* __restrict__ m,
                                const int*   __restrict__ ei,
                                float* __restrict__ s,
                                float* __restrict__ outp,
                                int E, int Etot) {
    int k = (blockIdx.x * blockDim.x + threadIdx.x) >> 5;
    if (k >= Etot) return;
    int lane = threadIdx.x & 31;
    int src, dst; edge_src_dst(ei, k, E, src, dst);
    float ex = 0.f;
    if (lane == 0) {
        ex = __expf(ebuf[k] - m[dst]);
        atomicAdd(&s[dst], ex);
    }
    ex = __shfl_sync(0xffffffffu, ex, 0);
    const float* xls = xl + (size_t)src * DPAD;
    float* orow = outp + (size_t)dst * DPAD;
    #pragma unroll
    for (int d = lane; d < DDIM; d += 32)
        atomicAdd(&orow[d], ex * xls[d]);
}

// ---------------- finalize: divide by s (+ optional relu) ------------------
__global__ void finalize_kernel(float* __restrict__ outp,
                                const float* __restrict__ s,
                                int n, int do_relu) {
    int i = blockIdx.x * blockDim.x + threadIdx.x;
    if (i >= n * DPAD) return;
    int node = i >> 8;       // /256
    int d = i & 255;
    if (d >= DDIM) return;
    float v = outp[i] / s[node];
    if (do_relu) v = fmaxf(v, 0.f);
    outp[i] = v;
}

// ---------------- head: out[q] = relu(dot(relu(A[q0]+B[q1]), Wm2)+bm2) -----
__global__ void head_kernel(const int* __restrict__ query,
                            const float* __restrict__ Atab,
                            const float* __restrict__ Btab,
                            const float* __restrict__ Wm2,
                            const float* __restrict__ bm2,
                            float* __restrict__ out, int Q) {
    int q = (blockIdx.x * blockDim.x + threadIdx.x) >> 5;
    if (q >= Q) return;
    int lane = threadIdx.x & 31;
    int q0 = query[2 * q], q1 = query[2 * q + 1];
    const float* a = Atab + (size_t)q0 * HDIM;
    const float* b = Btab + (size_t)q1 * HDIM;
    float partial = 0.f;
    #pragma unroll
    for (int j = lane; j < HDIM; j += 32) {
        float h = fmaxf(a[j] + b[j], 0.f);
        partial += h * Wm2[j];
    }
    #pragma unroll
    for (int off = 16; off; off >>= 1)
        partial += __shfl_down_sync(0xffffffffu, partial, off);
    if (lane == 0) out[q] = fmaxf(partial + bm2[0], 0.f);
}

// ---------------------------------------------------------------------------
extern "C" void kernel_launch(void* const* d_in, const int* in_sizes, int n_in,
                              void* d_out, int out_size) {
    const float* x    = (const float*)d_in[0];
    const int*   ei   = (const int*)  d_in[1];
    const int*   qry  = (const int*)  d_in[2];
    const float* W1l  = (const float*)d_in[3];
    const float* b1l  = (const float*)d_in[4];
    const float* W1r  = (const float*)d_in[5];
    const float* b1r  = (const float*)d_in[6];
    const float* att1 = (const float*)d_in[7];
    const float* W2l  = (const float*)d_in[8];
    const float* b2l  = (const float*)d_in[9];
    const float* W2r  = (const float*)d_in[10];
    const float* b2r  = (const float*)d_in[11];
    const float* att2 = (const float*)d_in[12];
    const float* Wm1  = (const float*)d_in[13];
    const float* bm1  = (const float*)d_in[14];
    const float* Wm2  = (const float*)d_in[15];
    const float* bm2  = (const float*)d_in[16];
    float* out = (float*)d_out;

    const int N = in_sizes[0] / FIN;        // 50000
    const int E = in_sizes[1] / 2;          // 800000
    const int Q = in_sizes[2] / 2;          // 200000
    const int Etot = E + N;

    float *p_xl, *p_xr, *p_h, *p_emb, *p_e, *p_m, *p_s;
    cudaGetSymbolAddress((void**)&p_xl,  g_xl);
    cudaGetSymbolAddress((void**)&p_xr,  g_xr);
    cudaGetSymbolAddress((void**)&p_h,   g_h);
    cudaGetSymbolAddress((void**)&p_emb, g_emb);
    cudaGetSymbolAddress((void**)&p_e,   g_e);
    cudaGetSymbolAddress((void**)&p_m,   g_m);
    cudaGetSymbolAddress((void**)&p_s,   g_s);

    const int TPB = 256;
    dim3 gemm_block(256);
    int edge_blocks = (Etot * 32 + TPB - 1) / TPB;
    int node_elem_blocks = (N * DPAD + TPB - 1) / TPB;

    // ================= Layer 1 =================
    {
        dim3 grid((DDIM + BN - 1) / BN, (N + BM - 1) / BM);
        gemm_bias_kernel<<<grid, gemm_block>>>(x, FIN, W1l, DDIM, b1l, p_xl, DPAD, N, FIN, DDIM);
        gemm_bias_kernel<<<grid, gemm_block>>>(x, FIN, W1r, DDIM, b1r, p_xr, DPAD, N, FIN, DDIM);
    }
    init_nodes_kernel<<<(N + TPB - 1) / TPB, TPB>>>(p_m, p_s, N);
    zero_kernel<<<2048, TPB>>>(p_h, N * DPAD);

    edge_e_kernel<<<edge_blocks, TPB>>>(p_xl, p_xr, att1, ei, p_e, p_m, E, Etot);
    edge_agg_kernel<<<edge_blocks, TPB>>>(p_xl, p_e, p_m, ei, p_s, p_h, E, Etot);
    finalize_kernel<<<node_elem_blocks, TPB>>>(p_h, p_s, N, 1);

    // ================= Layer 2 =================
    {
        dim3 grid((DDIM + BN - 1) / BN, (N + BM - 1) / BM);
        gemm_bias_kernel<<<grid, gemm_block>>>(p_h, DPAD, W2l, DDIM, b2l, p_xl, DPAD, N, DDIM, DDIM);
        gemm_bias_kernel<<<grid, gemm_block>>>(p_h, DPAD, W2r, DDIM, b2r, p_xr, DPAD, N, DDIM, DDIM);
    }
    init_nodes_kernel<<<(N + TPB - 1) / TPB, TPB>>>(p_m, p_s, N);
    zero_kernel<<<2048, TPB>>>(p_emb, N * DPAD);

    edge_e_kernel<<<edge_blocks, TPB>>>(p_xl, p_xr, att2, ei, p_e, p_m, E, Etot);
    edge_agg_kernel<<<edge_blocks, TPB>>>(p_xl, p_e, p_m, ei, p_s, p_emb, E, Etot);
    finalize_kernel<<<node_elem_blocks, TPB>>>(p_emb, p_s, N, 0);

    // ================= Head: A = emb@Wm1_top + bm1 ; B = emb@Wm1_bot =======
    {
        dim3 grid((HDIM + BN - 1) / BN, (N + BM - 1) / BM);
        gemm_bias_kernel<<<grid, gemm_block>>>(p_emb, DPAD, Wm1,               HDIM, bm1,     p_xl, HDIM, N, DDIM, HDIM);
        gemm_bias_kernel<<<grid, gemm_block>>>(p_emb, DPAD, Wm1 + DDIM * HDIM, HDIM, nullptr, p_xr, HDIM, N, DDIM, HDIM);
    }
    int q_blocks = (Q * 32 + TPB - 1) / TPB;
    head_kernel<<<q_blocks, TPB>>>(qry, p_xl, p_xr, Wm2, bm2, out, Q);
}

// round 2
// speedup vs baseline: 1.3526x; 1.3526x over previous
#include <cuda_runtime.h>
#include <math.h>
#include <float.h>

// Problem constants (shapes fixed by the dataset generator)
#define NNODES 50000
#define FIN    128
#define DDIM   250
#define DPAD   256
#define HDIM   256
#define EMAXT  850000   // E + N self loops

// ---------------- scratch (device globals; no runtime allocation) ----------
__device__ float g_xl [NNODES * DPAD];
__device__ float g_xr [NNODES * DPAD];
__device__ float g_h  [NNODES * DPAD];
__device__ float g_emb[NNODES * DPAD];
__device__ int   g_deg   [NNODES];
__device__ int   g_cursor[NNODES];
__device__ int   g_rowptr[NNODES + 1];
__device__ int   g_colsrc[EMAXT];

// ---------------- CSR build --------------------------------------------------
__global__ void zero_deg_kernel(int* deg, int n) {
    int i = blockIdx.x * blockDim.x + threadIdx.x;
    if (i < n) deg[i] = 0;
}

__global__ void hist_kernel(const int* __restrict__ ei, int* __restrict__ deg,
                            int E, int Etot) {
    int k = blockIdx.x * blockDim.x + threadIdx.x;
    if (k >= Etot) return;
    int dst = (k < E) ? ei[E + k] : (k - E);
    atomicAdd(&deg[dst], 1);
}

// single-block exclusive scan over n<=~64K elements, chunked by 1024
__global__ void scan_kernel(const int* __restrict__ deg,
                            int* __restrict__ rowptr,
                            int* __restrict__ cursor, int n) {
    __shared__ int buf[1024];
    __shared__ int carry;
    if (threadIdx.x == 0) { carry = 0; rowptr[0] = 0; }
    __syncthreads();
    for (int base = 0; base < n; base += 1024) {
        int i = base + threadIdx.x;
        int v = (i < n) ? deg[i] : 0;
        buf[threadIdx.x] = v;
        __syncthreads();
        for (int off = 1; off < 1024; off <<= 1) {
            int t = (threadIdx.x >= off) ? buf[threadIdx.x - off] : 0;
            __syncthreads();
            buf[threadIdx.x] += t;
            __syncthreads();
        }
        int incl = buf[threadIdx.x] + carry;
        if (i < n) { rowptr[i + 1] = incl; cursor[i] = incl - v; }
        __syncthreads();
        if (threadIdx.x == 1023) carry = incl;
        __syncthreads();
    }
}

__global__ void scatter_kernel(const int* __restrict__ ei,
                               int* __restrict__ cursor,
                               int* __restrict__ colsrc, int E, int Etot) {
    int k = blockIdx.x * blockDim.x + threadIdx.x;
    if (k >= Etot) return;
    int src, dst;
    if (k < E) { src = ei[k]; dst = ei[E + k]; }
    else       { src = k - E; dst = k - E; }
    int pos = atomicAdd(&cursor[dst], 1);
    colsrc[pos] = src;
}

// ---------------- tiled fp32 GEMM: C[M,N] = A[M,K]*B[K,N] (+bias) ----------
#define GBM 128
#define GBN 128
#define GBK 16
__global__ void __launch_bounds__(256, 2)
gemm128_kernel(const float* __restrict__ A, int lda,
               const float* __restrict__ B, int ldb,
               const float* __restrict__ bias,
               float* __restrict__ C, int ldc,
               int M, int K, int N) {
    __shared__ float As[GBK][GBM + 4];
    __shared__ float Bs[GBK][GBN + 4];
    int tid = threadIdx.x;            // 0..255
    int tx = tid % 16, ty = tid / 16;
    int row0 = blockIdx.y * GBM;
    int col0 = blockIdx.x * GBN;
    float acc[8][8] = {};

    for (int k0 = 0; k0 < K; k0 += GBK) {
        #pragma unroll
        for (int i = 0; i < 8; i++) {     // A tile: 128 x 16
            int idx = tid + i * 256;
            int m = idx / GBK, k = idx % GBK;
            int gm = row0 + m, gk = k0 + k;
            As[k][m] = (gm < M && gk < K) ? A[(size_t)gm * lda + gk] : 0.f;
        }
        #pragma unroll
        for (int i = 0; i < 8; i++) {     // B tile: 16 x 128
            int idx = tid + i * 256;
            int k = idx / GBN, nn = idx % GBN;
            int gk = k0 + k, gn = col0 + nn;
            Bs[k][nn] = (gk < K && gn < N) ? B[(size_t)gk * ldb + gn] : 0.f;
        }
        __syncthreads();
        #pragma unroll
        for (int k = 0; k < GBK; k++) {
            float a[8], b[8];
            #pragma unroll
            for (int i = 0; i < 8; i++) a[i] = As[k][ty * 8 + i];
            #pragma unroll
            for (int j = 0; j < 8; j++) b[j] = Bs[k][tx * 8 + j];
            #pragma unroll
            for (int i = 0; i < 8; i++)
                #pragma unroll
                for (int j = 0; j < 8; j++)
                    acc[i][j] += a[i] * b[j];
        }
        __syncthreads();
    }

    #pragma unroll
    for (int i = 0; i < 8; i++) {
        int gm = row0 + ty * 8 + i;
        if (gm >= M) continue;
        #pragma unroll
        for (int j = 0; j < 8; j++) {
            int gn = col0 + tx * 8 + j;
            if (gn >= N) continue;
            float v = acc[i][j];
            if (bias) v += bias[gn];
            C[(size_t)gm * ldc + gn] = v;
        }
    }
}

// ---------------- fused GATv2 softmax-aggregate: one warp per dst node ------
// online softmax over CSR edge list; out = sum(alpha * xl[src]) (/s), opt relu
__global__ void gat_agg_kernel(const float* __restrict__ xl,
                               const float* __restrict__ xr,
                               const float* __restrict__ att,
                               const int* __restrict__ rowptr,
                               const int* __restrict__ colsrc,
                               float* __restrict__ outp,
                               int n, int do_relu) {
    int w = (blockIdx.x * blockDim.x + threadIdx.x) >> 5;
    if (w >= n) return;
    int lane = threadIdx.x & 31;

    float attv[8], xrv[8], acc[8];
    #pragma unroll
    for (int j = 0; j < 8; j++) {
        int d = j * 32 + lane;
        bool ok = d < DDIM;
        attv[j] = ok ? att[d] : 0.f;
        xrv[j]  = ok ? xr[(size_t)w * DPAD + d] : 0.f;
        acc[j] = 0.f;
    }
    float m = -FLT_MAX, s = 0.f;
    int beg = rowptr[w], end = rowptr[w + 1];
    for (int p = beg; p < end; p++) {
        int src = colsrc[p];
        const float* xs = xl + (size_t)src * DPAD;
        float xv[8];
        float part = 0.f;
        #pragma unroll
        for (int j = 0; j < 8; j++) {
            int d = j * 32 + lane;
            float v = (d < DDIM) ? xs[d] : 0.f;
            xv[j] = v;
            float hsum = v + xrv[j];
            float lr = hsum > 0.f ? hsum : 0.2f * hsum;
            part += attv[j] * lr;
        }
        #pragma unroll
        for (int off = 16; off; off >>= 1)
            part += __shfl_xor_sync(0xffffffffu, part, off);
        float mn = fmaxf(m, part);
        float c   = __expf(m - mn);      // first iter: exp(-inf) -> 0
        float wgt = __expf(part - mn);
        s = s * c + wgt;
        #pragma unroll
        for (int j = 0; j < 8; j++) acc[j] = acc[j] * c + wgt * xv[j];
        m = mn;
    }
    float inv = 1.f / s;
    #pragma unroll
    for (int j = 0; j < 8; j++) {
        int d = j * 32 + lane;
        if (d < DDIM) {
            float v = acc[j] * inv;
            if (do_relu) v = fmaxf(v, 0.f);
            outp[(size_t)w * DPAD + d] = v;
        }
    }
}

// ---------------- head: out[q] = relu(dot(relu(A[q0]+B[q1]), Wm2)+bm2) -----
__global__ void head_kernel(const int* __restrict__ query,
                            const float* __restrict__ Atab,
                            const float* __restrict__ Btab,
                            const float* __restrict__ Wm2,
                            const float* __restrict__ bm2,
                            float* __restrict__ out, int Q) {
    int q = (blockIdx.x * blockDim.x + threadIdx.x) >> 5;
    if (q >= Q) return;
    int lane = threadIdx.x & 31;
    int q0 = query[2 * q], q1 = query[2 * q + 1];
    const float* a = Atab + (size_t)q0 * HDIM;
    const float* b = Btab + (size_t)q1 * HDIM;
    float partial = 0.f;
    #pragma unroll
    for (int j = lane; j < HDIM; j += 32) {
        float h = fmaxf(a[j] + b[j], 0.f);
        partial += h * Wm2[j];
    }
    #pragma unroll
    for (int off = 16; off; off >>= 1)
        partial += __shfl_down_sync(0xffffffffu, partial, off);
    if (lane == 0) out[q] = fmaxf(partial + bm2[0], 0.f);
}

// ---------------------------------------------------------------------------
extern "C" void kernel_launch(void* const* d_in, const int* in_sizes, int n_in,
                              void* d_out, int out_size) {
    const float* x    = (const float*)d_in[0];
    const int*   ei   = (const int*)  d_in[1];
    const int*   qry  = (const int*)  d_in[2];
    const float* W1l  = (const float*)d_in[3];
    const float* b1l  = (const float*)d_in[4];
    const float* W1r  = (const float*)d_in[5];
    const float* b1r  = (const float*)d_in[6];
    const float* att1 = (const float*)d_in[7];
    const float* W2l  = (const float*)d_in[8];
    const float* b2l  = (const float*)d_in[9];
    const float* W2r  = (const float*)d_in[10];
    const float* b2r  = (const float*)d_in[11];
    const float* att2 = (const float*)d_in[12];
    const float* Wm1  = (const float*)d_in[13];
    const float* bm1  = (const float*)d_in[14];
    const float* Wm2  = (const float*)d_in[15];
    const float* bm2  = (const float*)d_in[16];
    float* out = (float*)d_out;

    const int N = in_sizes[0] / FIN;        // 50000
    const int E = in_sizes[1] / 2;          // 800000
    const int Q = in_sizes[2] / 2;          // 200000
    const int Etot = E + N;

    float *p_xl, *p_xr, *p_h, *p_emb;
    int *p_deg, *p_cursor, *p_rowptr, *p_colsrc;
    cudaGetSymbolAddress((void**)&p_xl,     g_xl);
    cudaGetSymbolAddress((void**)&p_xr,     g_xr);
    cudaGetSymbolAddress((void**)&p_h,      g_h);
    cudaGetSymbolAddress((void**)&p_emb,    g_emb);
    cudaGetSymbolAddress((void**)&p_deg,    g_deg);
    cudaGetSymbolAddress((void**)&p_cursor, g_cursor);
    cudaGetSymbolAddress((void**)&p_rowptr, g_rowptr);
    cudaGetSymbolAddress((void**)&p_colsrc, g_colsrc);

    const int TPB = 256;
    int agg_blocks = (N * 32 + TPB - 1) / TPB;

    // ---------- CSR build (per launch; deterministic work) ----------
    zero_deg_kernel<<<(N + TPB - 1) / TPB, TPB>>>(p_deg, N);
    hist_kernel<<<(Etot + TPB - 1) / TPB, TPB>>>(ei, p_deg, E, Etot);
    scan_kernel<<<1, 1024>>>(p_deg, p_rowptr, p_cursor, N);
    scatter_kernel<<<(Etot + TPB - 1) / TPB, TPB>>>(ei, p_cursor, p_colsrc, E, Etot);

    // ---------- Layer 1 ----------
    {
        dim3 grid((DDIM + GBN - 1) / GBN, (N + GBM - 1) / GBM);
        gemm128_kernel<<<grid, 256>>>(x, FIN, W1l, DDIM, b1l, p_xl, DPAD, N, FIN, DDIM);
        gemm128_kernel<<<grid, 256>>>(x, FIN, W1r, DDIM, b1r, p_xr, DPAD, N, FIN, DDIM);
    }
    gat_agg_kernel<<<agg_blocks, TPB>>>(p_xl, p_xr, att1, p_rowptr, p_colsrc, p_h, N, 1);

    // ---------- Layer 2 ----------
    {
        dim3 grid((DDIM + GBN - 1) / GBN, (N + GBM - 1) / GBM);
        gemm128_kernel<<<grid, 256>>>(p_h, DPAD, W2l, DDIM, b2l, p_xl, DPAD, N, DDIM, DDIM);
        gemm128_kernel<<<grid, 256>>>(p_h, DPAD, W2r, DDIM, b2r, p_xr, DPAD, N, DDIM, DDIM);
    }
    gat_agg_kernel<<<agg_blocks, TPB>>>(p_xl, p_xr, att2, p_rowptr, p_colsrc, p_emb, N, 0);

    // ---------- Head: A = emb@Wm1_top + bm1 ; B = emb@Wm1_bot ----------
    {
        dim3 grid((HDIM + GBN - 1) / GBN, (N + GBM - 1) / GBM);
        gemm128_kernel<<<grid, 256>>>(p_emb, DPAD, Wm1,               HDIM, bm1,     p_xl, HDIM, N, DDIM, HDIM);
        gemm128_kernel<<<grid, 256>>>(p_emb, DPAD, Wm1 + DDIM * HDIM, HDIM, nullptr, p_xr, HDIM, N, DDIM, HDIM);
    }
    int q_blocks = (Q * 32 + TPB - 1) / TPB;
    head_kernel<<<q_blocks, TPB>>>(qry, p_xl, p_xr, Wm2, bm2, out, Q);
}

// round 3
// speedup vs baseline: 1.3854x; 1.0242x over previous
#include <cuda_runtime.h>
#include <math.h>
#include <float.h>

// Problem constants (shapes fixed by the dataset generator)
#define NNODES 50000
#define FIN    128
#define DDIM   250
#define DPAD   256
#define HDIM   256
#define EMAXT  850000   // E + N self loops

// ---------------- scratch (device globals; no runtime allocation) ----------
__device__ float g_xl [NNODES * DPAD];
__device__ float g_xr [NNODES * DPAD];
__device__ float g_h  [NNODES * DPAD];
__device__ float g_emb[NNODES * DPAD];
__device__ int   g_deg   [NNODES];
__device__ int   g_cursor[NNODES];
__device__ int   g_rowptr[NNODES + 1];
__device__ int   g_colsrc[EMAXT];

// ---------------- packed fp32x2 FMA (sm_103a; ptxas won't auto-fuse) -------
__device__ __forceinline__ float2 ffma2(float2 a, float2 b, float2 c) {
    unsigned long long aa = *(unsigned long long*)&a;
    unsigned long long bb = *(unsigned long long*)&b;
    unsigned long long cc = *(unsigned long long*)&c;
    unsigned long long dd;
    asm("fma.rn.f32x2 %0, %1, %2, %3;" : "=l"(dd) : "l"(aa), "l"(bb), "l"(cc));
    return *(float2*)&dd;
}

// ---------------- CSR build --------------------------------------------------
__global__ void zero_deg_kernel(int* deg, int n) {
    int i = blockIdx.x * blockDim.x + threadIdx.x;
    if (i < n) deg[i] = 0;
}

__global__ void hist_kernel(const int* __restrict__ ei, int* __restrict__ deg,
                            int E, int Etot) {
    int k = blockIdx.x * blockDim.x + threadIdx.x;
    if (k >= Etot) return;
    int dst = (k < E) ? ei[E + k] : (k - E);
    atomicAdd(&deg[dst], 1);
}

// single-block exclusive scan (shfl-based), chunked by 1024
__global__ void scan_kernel(const int* __restrict__ deg,
                            int* __restrict__ rowptr,
                            int* __restrict__ cursor, int n) {
    __shared__ int wpre[32];
    __shared__ int carry;
    int lane = threadIdx.x & 31, wid = threadIdx.x >> 5;
    if (threadIdx.x == 0) { carry = 0; rowptr[0] = 0; }
    __syncthreads();
    for (int base = 0; base < n; base += 1024) {
        int i = base + threadIdx.x;
        int v = (i < n) ? deg[i] : 0;
        int x = v;
        #pragma unroll
        for (int off = 1; off < 32; off <<= 1) {
            int t = __shfl_up_sync(0xffffffffu, x, off);
            if (lane >= off) x += t;
        }
        if (lane == 31) wpre[wid] = x;
        __syncthreads();
        if (wid == 0) {
            int y = wpre[lane];
            #pragma unroll
            for (int off = 1; off < 32; off <<= 1) {
                int t = __shfl_up_sync(0xffffffffu, y, off);
                if (lane >= off) y += t;
            }
            wpre[lane] = y;
        }
        __syncthreads();
        int warpoff = (wid == 0) ? 0 : wpre[wid - 1];
        int incl = x + warpoff + carry;
        if (i < n) { rowptr[i + 1] = incl; cursor[i] = incl - v; }
        __syncthreads();
        if (threadIdx.x == 1023) carry = incl;
        __syncthreads();
    }
}

__global__ void scatter_kernel(const int* __restrict__ ei,
                               int* __restrict__ cursor,
                               int* __restrict__ colsrc, int E, int Etot) {
    int k = blockIdx.x * blockDim.x + threadIdx.x;
    if (k >= Etot) return;
    int src, dst;
    if (k < E) { src = ei[k]; dst = ei[E + k]; }
    else       { src = k - E; dst = k - E; }
    int pos = atomicAdd(&cursor[dst], 1);
    colsrc[pos] = src;
}

// ---------------- tiled fp32 GEMM (FFMA2 mainloop) -------------------------
#define GBM 128
#define GBN 128
#define GBK 16
__global__ void __launch_bounds__(256, 2)
gemm128_kernel(const float* __restrict__ A, int lda,
               const float* __restrict__ B, int ldb,
               const float* __restrict__ bias,
               float* __restrict__ C, int ldc,
               int M, int K, int N) {
    __shared__ __align__(16) float As[GBK][GBM + 4];
    __shared__ __align__(16) float Bs[GBK][GBN + 4];
    int tid = threadIdx.x;            // 0..255
    int tx = tid % 16, ty = tid / 16;
    int row0 = blockIdx.y * GBM;
    int col0 = blockIdx.x * GBN;
    float2 acc[4][8];                 // rows paired: (ty*8+2i, ty*8+2i+1) x col (tx*8+j)
    #pragma unroll
    for (int i = 0; i < 4; i++)
        #pragma unroll
        for (int j = 0; j < 8; j++) acc[i][j] = make_float2(0.f, 0.f);

    for (int k0 = 0; k0 < K; k0 += GBK) {
        #pragma unroll
        for (int i = 0; i < 8; i++) {     // A tile: 128 x 16
            int idx = tid + i * 256;
            int m = idx / GBK, k = idx % GBK;
            int gm = row0 + m, gk = k0 + k;
            As[k][m] = (gm < M && gk < K) ? A[(size_t)gm * lda + gk] : 0.f;
        }
        #pragma unroll
        for (int i = 0; i < 8; i++) {     // B tile: 16 x 128
            int idx = tid + i * 256;
            int k = idx / GBN, nn = idx % GBN;
            int gk = k0 + k, gn = col0 + nn;
            Bs[k][nn] = (gk < K && gn < N) ? B[(size_t)gk * ldb + gn] : 0.f;
        }
        __syncthreads();
        #pragma unroll
        for (int k = 0; k < GBK; k++) {
            float4 a01 = *(const float4*)&As[k][ty * 8];
            float4 a45 = *(const float4*)&As[k][ty * 8 + 4];
            float2 a2[4] = { make_float2(a01.x, a01.y), make_float2(a01.z, a01.w),
                             make_float2(a45.x, a45.y), make_float2(a45.z, a45.w) };
            float4 b03 = *(const float4*)&Bs[k][tx * 8];
            float4 b47 = *(const float4*)&Bs[k][tx * 8 + 4];
            float bs[8] = { b03.x, b03.y, b03.z, b03.w, b47.x, b47.y, b47.z, b47.w };
            #pragma unroll
            for (int j = 0; j < 8; j++) {
                float2 bd = make_float2(bs[j], bs[j]);
                #pragma unroll
                for (int i = 0; i < 4; i++)
                    acc[i][j] = ffma2(a2[i], bd, acc[i][j]);
            }
        }
        __syncthreads();
    }

    #pragma unroll
    for (int i = 0; i < 4; i++) {
        int r0 = row0 + ty * 8 + 2 * i;
        #pragma unroll
        for (int j = 0; j < 8; j++) {
            int gn = col0 + tx * 8 + j;
            if (gn >= N) continue;
            float bv = bias ? bias[gn] : 0.f;
            if (r0 < M)     C[(size_t)r0 * ldc + gn]       = acc[i][j].x + bv;
            if (r0 + 1 < M) C[(size_t)(r0 + 1) * ldc + gn] = acc[i][j].y + bv;
        }
    }
}

// ---------------- fused GATv2 softmax-aggregate: one warp per dst node ------
__global__ void gat_agg_kernel(const float* __restrict__ xl,
                               const float* __restrict__ xr,
                               const float* __restrict__ att,
                               const int* __restrict__ rowptr,
                               const int* __restrict__ colsrc,
                               float* __restrict__ outp,
                               int n, int do_relu) {
    int w = (blockIdx.x * blockDim.x + threadIdx.x) >> 5;
    if (w >= n) return;
    int lane = threadIdx.x & 31;

    float attv[8], xrv[8], acc[8];
    #pragma unroll
    for (int j = 0; j < 8; j++) {
        int d = j * 32 + lane;
        bool ok = d < DDIM;
        attv[j] = ok ? att[d] : 0.f;
        xrv[j]  = ok ? xr[(size_t)w * DPAD + d] : 0.f;
        acc[j] = 0.f;
    }
    float m = -FLT_MAX, s = 0.f;
    int beg = rowptr[w], end = rowptr[w + 1];
    for (int p = beg; p < end; p++) {
        int src = colsrc[p];
        const float* xs = xl + (size_t)src * DPAD;
        float xv[8];
        float part = 0.f;
        #pragma unroll
        for (int j = 0; j < 8; j++) {
            int d = j * 32 + lane;
            float v = (d < DDIM) ? xs[d] : 0.f;
            xv[j] = v;
            float hsum = v + xrv[j];
            float lr = hsum > 0.f ? hsum : 0.2f * hsum;
            part += attv[j] * lr;
        }
        #pragma unroll
        for (int off = 16; off; off >>= 1)
            part += __shfl_xor_sync(0xffffffffu, part, off);
        float mn = fmaxf(m, part);
        float c   = __expf(m - mn);
        float wgt = __expf(part - mn);
        s = s * c + wgt;
        #pragma unroll
        for (int j = 0; j < 8; j++) acc[j] = acc[j] * c + wgt * xv[j];
        m = mn;
    }
    float inv = 1.f / s;
    #pragma unroll
    for (int j = 0; j < 8; j++) {
        int d = j * 32 + lane;
        if (d < DDIM) {
            float v = acc[j] * inv;
            if (do_relu) v = fmaxf(v, 0.f);
            outp[(size_t)w * DPAD + d] = v;
        }
    }
}

// ---------------- head: out[q] = relu(dot(relu(A[q0]+B[q1]), Wm2)+bm2) -----
__global__ void head_kernel(const int* __restrict__ query,
                            const float* __restrict__ Atab,
                            const float* __restrict__ Btab,
                            const float* __restrict__ Wm2,
                            const float* __restrict__ bm2,
                            float* __restrict__ out, int Q) {
    int q = (blockIdx.x * blockDim.x + threadIdx.x) >> 5;
    if (q >= Q) return;
    int lane = threadIdx.x & 31;
    int q0 = query[2 * q], q1 = query[2 * q + 1];
    const float* a = Atab + (size_t)q0 * HDIM;
    const float* b = Btab + (size_t)q1 * HDIM;
    float partial = 0.f;
    #pragma unroll
    for (int j = lane; j < HDIM; j += 32) {
        float h = fmaxf(a[j] + b[j], 0.f);
        partial += h * Wm2[j];
    }
    #pragma unroll
    for (int off = 16; off; off >>= 1)
        partial += __shfl_down_sync(0xffffffffu, partial, off);
    if (lane == 0) out[q] = fmaxf(partial + bm2[0], 0.f);
}

// ---------------------------------------------------------------------------
extern "C" void kernel_launch(void* const* d_in, const int* in_sizes, int n_in,
                              void* d_out, int out_size) {
    const float* x    = (const float*)d_in[0];
    const int*   ei   = (const int*)  d_in[1];
    const int*   qry  = (const int*)  d_in[2];
    const float* W1l  = (const float*)d_in[3];
    const float* b1l  = (const float*)d_in[4];
    const float* W1r  = (const float*)d_in[5];
    const float* b1r  = (const float*)d_in[6];
    const float* att1 = (const float*)d_in[7];
    const float* W2l  = (const float*)d_in[8];
    const float* b2l  = (const float*)d_in[9];
    const float* W2r  = (const float*)d_in[10];
    const float* b2r  = (const float*)d_in[11];
    const float* att2 = (const float*)d_in[12];
    const float* Wm1  = (const float*)d_in[13];
    const float* bm1  = (const float*)d_in[14];
    const float* Wm2  = (const float*)d_in[15];
    const float* bm2  = (const float*)d_in[16];
    float* out = (float*)d_out;

    const int N = in_sizes[0] / FIN;        // 50000
    const int E = in_sizes[1] / 2;          // 800000
    const int Q = in_sizes[2] / 2;          // 200000
    const int Etot = E + N;

    float *p_xl, *p_xr, *p_h, *p_emb;
    int *p_deg, *p_cursor, *p_rowptr, *p_colsrc;
    cudaGetSymbolAddress((void**)&p_xl,     g_xl);
    cudaGetSymbolAddress((void**)&p_xr,     g_xr);
    cudaGetSymbolAddress((void**)&p_h,      g_h);
    cudaGetSymbolAddress((void**)&p_emb,    g_emb);
    cudaGetSymbolAddress((void**)&p_deg,    g_deg);
    cudaGetSymbolAddress((void**)&p_cursor, g_cursor);
    cudaGetSymbolAddress((void**)&p_rowptr, g_rowptr);
    cudaGetSymbolAddress((void**)&p_colsrc, g_colsrc);

    const int TPB = 256;
    int agg_blocks = (N * 32 + TPB - 1) / TPB;

    // ---------- CSR build ----------
    zero_deg_kernel<<<(N + TPB - 1) / TPB, TPB>>>(p_deg, N);
    hist_kernel<<<(Etot + TPB - 1) / TPB, TPB>>>(ei, p_deg, E, Etot);
    scan_kernel<<<1, 1024>>>(p_deg, p_rowptr, p_cursor, N);
    scatter_kernel<<<(Etot + TPB - 1) / TPB, TPB>>>(ei, p_cursor, p_colsrc, E, Etot);

    // ---------- Layer 1 ----------
    {
        dim3 grid((DDIM + GBN - 1) / GBN, (N + GBM - 1) / GBM);
        gemm128_kernel<<<grid, 256>>>(x, FIN, W1l, DDIM, b1l, p_xl, DPAD, N, FIN, DDIM);
        gemm128_kernel<<<grid, 256>>>(x, FIN, W1r, DDIM, b1r, p_xr, DPAD, N, FIN, DDIM);
    }
    gat_agg_kernel<<<agg_blocks, TPB>>>(p_xl, p_xr, att1, p_rowptr, p_colsrc, p_h, N, 1);

    // ---------- Layer 2 ----------
    {
        dim3 grid((DDIM + GBN - 1) / GBN, (N + GBM - 1) / GBM);
        gemm128_kernel<<<grid, 256>>>(p_h, DPAD, W2l, DDIM, b2l, p_xl, DPAD, N, DDIM, DDIM);
        gemm128_kernel<<<grid, 256>>>(p_h, DPAD, W2r, DDIM, b2r, p_xr, DPAD, N, DDIM, DDIM);
    }
    gat_agg_kernel<<<agg_blocks, TPB>>>(p_xl, p_xr, att2, p_rowptr, p_colsrc, p_emb, N, 0);

    // ---------- Head: A = emb@Wm1_top + bm1 ; B = emb@Wm1_bot ----------
    {
        dim3 grid((HDIM + GBN - 1) / GBN, (N + GBM - 1) / GBM);
        gemm128_kernel<<<grid, 256>>>(p_emb, DPAD, Wm1,               HDIM, bm1,     p_xl, HDIM, N, DDIM, HDIM);
        gemm128_kernel<<<grid, 256>>>(p_emb, DPAD, Wm1 + DDIM * HDIM, HDIM, nullptr, p_xr, HDIM, N, DDIM, HDIM);
    }
    int q_blocks = (Q * 32 + TPB - 1) / TPB;
    head_kernel<<<q_blocks, TPB>>>(qry, p_xl, p_xr, Wm2, bm2, out, Q);
}

// round 5
// speedup vs baseline: 1.6922x; 1.2214x over previous
#include <cuda_runtime.h>
#include <cuda_bf16.h>
#include <math.h>
#include <float.h>

// Problem constants (shapes fixed by the dataset generator)
#define NNODES 50000
#define FIN    128
#define DDIM   250
#define DPAD   256
#define HDIM   256
#define EMAXT  850000   // E + N self loops

// ---------------- scratch (device globals; no runtime allocation) ----------
__device__ float g_xl [NNODES * DPAD];
__device__ float g_xr [NNODES * DPAD];
__device__ float g_h  [NNODES * DPAD];
__device__ float g_emb[NNODES * DPAD];
__device__ int   g_deg   [NNODES];
__device__ int   g_cursor[NNODES];
__device__ int   g_rowptr[NNODES + 1];
__device__ int   g_colsrc[EMAXT];
// split-bf16 buffers
__device__ __align__(16) __nv_bfloat16 g_ahi[NNODES * DPAD];
__device__ __align__(16) __nv_bfloat16 g_alo[NNODES * DPAD];
__device__ __align__(16) __nv_bfloat16 g_bthi[2][256 * 256];  // [n][k] transposed weights
__device__ __align__(16) __nv_bfloat16 g_btlo[2][256 * 256];

// ---------------- CSR build ------------------------------------------------
__global__ void zero_deg_kernel(int* deg, int n) {
    int i = blockIdx.x * blockDim.x + threadIdx.x;
    if (i < n) deg[i] = 0;
}

__global__ void hist_kernel(const int* __restrict__ ei, int* __restrict__ deg,
                            int E, int Etot) {
    int k = blockIdx.x * blockDim.x + threadIdx.x;
    if (k >= Etot) return;
    int dst = (k < E) ? ei[E + k] : (k - E);
    atomicAdd(&deg[dst], 1);
}

// single-block exclusive scan (shfl-based), chunked by 1024
__global__ void scan_kernel(const int* __restrict__ deg,
                            int* __restrict__ rowptr,
                            int* __restrict__ cursor, int n) {
    __shared__ int wpre[32];
    __shared__ int carry;
    int lane = threadIdx.x & 31, wid = threadIdx.x >> 5;
    if (threadIdx.x == 0) { carry = 0; rowptr[0] = 0; }
    __syncthreads();
    for (int base = 0; base < n; base += 1024) {
        int i = base + threadIdx.x;
        int v = (i < n) ? deg[i] : 0;
        int x = v;
        #pragma unroll
        for (int off = 1; off < 32; off <<= 1) {
            int t = __shfl_up_sync(0xffffffffu, x, off);
            if (lane >= off) x += t;
        }
        if (lane == 31) wpre[wid] = x;
        __syncthreads();
        if (wid == 0) {
            int y = wpre[lane];
            #pragma unroll
            for (int off = 1; off < 32; off <<= 1) {
                int t = __shfl_up_sync(0xffffffffu, y, off);
                if (lane >= off) y += t;
            }
            wpre[lane] = y;
        }
        __syncthreads();
        int warpoff = (wid == 0) ? 0 : wpre[wid - 1];
        int incl = x + warpoff + carry;
        if (i < n) { rowptr[i + 1] = incl; cursor[i] = incl - v; }
        __syncthreads();
        if (threadIdx.x == 1023) carry = incl;
        __syncthreads();
    }
}

__global__ void scatter_kernel(const int* __restrict__ ei,
                               int* __restrict__ cursor,
                               int* __restrict__ colsrc, int E, int Etot) {
    int k = blockIdx.x * blockDim.x + threadIdx.x;
    if (k >= Etot) return;
    int src, dst;
    if (k < E) { src = ei[k]; dst = ei[E + k]; }
    else       { src = k - E; dst = k - E; }
    int pos = atomicAdd(&cursor[dst], 1);
    colsrc[pos] = src;
}

// ---------------- split-bf16 conversions -----------------------------------
__global__ void conv_act_kernel(const float* __restrict__ A, int lda,
                                int Kreal, int Kpad, int M,
                                __nv_bfloat16* __restrict__ hi,
                                __nv_bfloat16* __restrict__ lo) {
    int idx = blockIdx.x * blockDim.x + threadIdx.x;
    int total = M * Kpad;
    int stride = gridDim.x * blockDim.x;
    for (; idx < total; idx += stride) {
        int row = idx / Kpad, k = idx - row * Kpad;
        float v = (k < Kreal) ? A[(size_t)row * lda + k] : 0.f;
        __nv_bfloat16 h = __float2bfloat16(v);
        float r = v - __bfloat162float(h);
        hi[idx] = h;
        lo[idx] = __float2bfloat16(r);
    }
}

// weights: fp32 W [K x Nreal] (row stride ldw) -> transposed hi/lo bf16 [256 x Kpad]
__global__ void conv_wt_kernel(const float* __restrict__ W, int ldw,
                               int Kreal, int Nreal, int Kpad,
                               __nv_bfloat16* __restrict__ hi,
                               __nv_bfloat16* __restrict__ lo) {
    int idx = blockIdx.x * blockDim.x + threadIdx.x;
    int total = 256 * Kpad;
    if (idx >= total) return;
    int n = idx / Kpad, k = idx - n * Kpad;
    float v = (n < Nreal && k < Kreal) ? W[(size_t)k * ldw + n] : 0.f;
    __nv_bfloat16 h = __float2bfloat16(v);
    float r = v - __bfloat162float(h);
    hi[idx] = h;
    lo[idx] = __float2bfloat16(r);
}

// ---------------- bf16 mma.sync helper -------------------------------------
__device__ __forceinline__ void mma16816(float* c, const unsigned* a,
                                         unsigned b0, unsigned b1) {
    asm volatile(
        "mma.sync.aligned.m16n8k16.row.col.f32.bf16.bf16.f32 "
        "{%0,%1,%2,%3},{%4,%5,%6,%7},{%8,%9},{%0,%1,%2,%3};"
        : "+f"(c[0]), "+f"(c[1]), "+f"(c[2]), "+f"(c[3])
        : "r"(a[0]), "r"(a[1]), "r"(a[2]), "r"(a[3]), "r"(b0), "r"(b1));
}

// ---------------- split-bf16 tensor-core GEMM ------------------------------
// C[M x Nreal] = A[M x K] * B[K x Nreal] (+bias); A as hi/lo bf16 [M x Kpad],
// B as transposed hi/lo bf16 [256 x Kpad]. Tile 128x128, 8 warps.
#define SROW 40   // bf16 elements per smem row (32 k + 8 pad)
__global__ void __launch_bounds__(256)
gemm_mma_kernel(const __nv_bfloat16* __restrict__ Ahi,
                const __nv_bfloat16* __restrict__ Alo, int Kpad,
                const __nv_bfloat16* __restrict__ BThi,
                const __nv_bfloat16* __restrict__ BTlo,
                const float* __restrict__ bias,
                float* __restrict__ C, int ldc, int M, int Nreal) {
    __shared__ __align__(16) __nv_bfloat16 sAh[128 * SROW];
    __shared__ __align__(16) __nv_bfloat16 sAl[128 * SROW];
    __shared__ __align__(16) __nv_bfloat16 sBh[128 * SROW];
    __shared__ __align__(16) __nv_bfloat16 sBl[128 * SROW];

    int tid = threadIdx.x;
    int lane = tid & 31, wid = tid >> 5;
    int g = lane >> 2, tk = lane & 3;
    int wm = (wid & 3) * 32;       // warp row offset in tile
    int wn = (wid >> 2) * 64;      // warp col offset in tile
    int row0 = blockIdx.y * 128;
    int col0 = blockIdx.x * 128;

    float acc[2][8][4];
    #pragma unroll
    for (int i = 0; i < 2; i++)
        #pragma unroll
        for (int j = 0; j < 8; j++)
            #pragma unroll
            for (int q = 0; q < 4; q++) acc[i][j][q] = 0.f;

    for (int k0 = 0; k0 < Kpad; k0 += 32) {
        // stage 128x32 of each matrix: 512 slots x 8 bf16 (uint4) = 4096 elems
        #pragma unroll
        for (int it = 0; it < 2; it++) {
            int f = tid + it * 256;
            int r = f >> 2, kg = f & 3;          // r: 0..127, kg: 0..3 (8 elems each)
            int soff = r * SROW + kg * 8;
            size_t aoff = (size_t)(row0 + r) * Kpad + k0 + kg * 8;
            uint4 vh = make_uint4(0, 0, 0, 0), vl = make_uint4(0, 0, 0, 0);
            if (row0 + r < M) {
                vh = *(const uint4*)(Ahi + aoff);
                vl = *(const uint4*)(Alo + aoff);
            }
            *(uint4*)&sAh[soff] = vh;
            *(uint4*)&sAl[soff] = vl;
            size_t boff = (size_t)(col0 + r) * Kpad + k0 + kg * 8;
            *(uint4*)&sBh[soff] = *(const uint4*)(BThi + boff);
            *(uint4*)&sBl[soff] = *(const uint4*)(BTlo + boff);
        }
        __syncthreads();

        #pragma unroll
        for (int kk = 0; kk < 32; kk += 16) {
            unsigned ah[2][4], al[2][4];
            #pragma unroll
            for (int mf = 0; mf < 2; mf++) {
                int base = (wm + mf * 16 + g) * SROW + kk + 2 * tk;
                ah[mf][0] = *(const unsigned*)&sAh[base];
                ah[mf][1] = *(const unsigned*)&sAh[base + 8 * SROW];
                ah[mf][2] = *(const unsigned*)&sAh[base + 8];
                ah[mf][3] = *(const unsigned*)&sAh[base + 8 * SROW + 8];
                al[mf][0] = *(const unsigned*)&sAl[base];
                al[mf][1] = *(const unsigned*)&sAl[base + 8 * SROW];
                al[mf][2] = *(const unsigned*)&sAl[base + 8];
                al[mf][3] = *(const unsigned*)&sAl[base + 8 * SROW + 8];
            }
            #pragma unroll
            for (int nf = 0; nf < 8; nf++) {
                int bb = (wn + nf * 8 + g) * SROW + kk + 2 * tk;
                unsigned bh0 = *(const unsigned*)&sBh[bb];
                unsigned bh1 = *(const unsigned*)&sBh[bb + 8];
                unsigned bl0 = *(const unsigned*)&sBl[bb];
                unsigned bl1 = *(const unsigned*)&sBl[bb + 8];
                #pragma unroll
                for (int mf = 0; mf < 2; mf++) {
                    mma16816(acc[mf][nf], ah[mf], bh0, bh1);  // hi*hi
                    mma16816(acc[mf][nf], al[mf], bh0, bh1);  // lo*hi
                    mma16816(acc[mf][nf], ah[mf], bl0, bl1);  // hi*lo
                }
            }
        }
        __syncthreads();
    }

    // epilogue
    #pragma unroll
    for (int mf = 0; mf < 2; mf++) {
        #pragma unroll
        for (int nf = 0; nf < 8; nf++) {
            int col = col0 + wn + nf * 8 + 2 * tk;
            if (col >= Nreal) continue;          // cols even, Nreal even -> col+1 valid
            float bv0 = bias ? bias[col]     : 0.f;
            float bv1 = bias ? bias[col + 1] : 0.f;
            int r = row0 + wm + mf * 16 + g;
            if (r < M) {
                float2 v = make_float2(acc[mf][nf][0] + bv0, acc[mf][nf][1] + bv1);
                *(float2*)&C[(size_t)r * ldc + col] = v;
            }
            int r2 = r + 8;
            if (r2 < M) {
                float2 v = make_float2(acc[mf][nf][2] + bv0, acc[mf][nf][3] + bv1);
                *(float2*)&C[(size_t)r2 * ldc + col] = v;
            }
        }
    }
}

// ---------------- fused GATv2 softmax-aggregate: one warp per dst node ------
__global__ void gat_agg_kernel(const float* __restrict__ xl,
                               const float* __restrict__ xr,
                               const float* __restrict__ att,
                               const int* __restrict__ rowptr,
                               const int* __restrict__ colsrc,
                               float* __restrict__ outp,
                               int n, int do_relu) {
    int w = (blockIdx.x * blockDim.x + threadIdx.x) >> 5;
    if (w >= n) return;
    int lane = threadIdx.x & 31;

    float attv[8], xrv[8], acc[8];
    #pragma unroll
    for (int j = 0; j < 8; j++) {
        int d = j * 32 + lane;
        bool ok = d < DDIM;
        attv[j] = ok ? att[d] : 0.f;
        xrv[j]  = ok ? xr[(size_t)w * DPAD + d] : 0.f;
        acc[j] = 0.f;
    }
    float m = -FLT_MAX, s = 0.f;
    int beg = rowptr[w], end = rowptr[w + 1];
    for (int p = beg; p < end; p++) {
        int src = colsrc[p];
        const float* xs = xl + (size_t)src * DPAD;
        float xv[8];
        float part = 0.f;
        #pragma unroll
        for (int j = 0; j < 8; j++) {
            int d = j * 32 + lane;
            float v = (d < DDIM) ? xs[d] : 0.f;
            xv[j] = v;
            float hsum = v + xrv[j];
            float lr = hsum > 0.f ? hsum : 0.2f * hsum;
            part += attv[j] * lr;
        }
        #pragma unroll
        for (int off = 16; off; off >>= 1)
            part += __shfl_xor_sync(0xffffffffu, part, off);
        float mn = fmaxf(m, part);
        float c   = __expf(m - mn);
        float wgt = __expf(part - mn);
        s = s * c + wgt;
        #pragma unroll
        for (int j = 0; j < 8; j++) acc[j] = acc[j] * c + wgt * xv[j];
        m = mn;
    }
    float inv = 1.f / s;
    #pragma unroll
    for (int j = 0; j < 8; j++) {
        int d = j * 32 + lane;
        if (d < DDIM) {
            float v = acc[j] * inv;
            if (do_relu) v = fmaxf(v, 0.f);
            outp[(size_t)w * DPAD + d] = v;
        }
    }
}

// ---------------- head: out[q] = relu(dot(relu(A[q0]+B[q1]), Wm2)+bm2) -----
__global__ void head_kernel(const int* __restrict__ query,
                            const float* __restrict__ Atab,
                            const float* __restrict__ Btab,
                            const float* __restrict__ Wm2,
                            const float* __restrict__ bm2,
                            float* __restrict__ out, int Q) {
    int q = (blockIdx.x * blockDim.x + threadIdx.x) >> 5;
    if (q >= Q) return;
    int lane = threadIdx.x & 31;
    int q0 = query[2 * q], q1 = query[2 * q + 1];
    const float* a = Atab + (size_t)q0 * HDIM;
    const float* b = Btab + (size_t)q1 * HDIM;
    float partial = 0.f;
    #pragma unroll
    for (int j = lane; j < HDIM; j += 32) {
        float h = fmaxf(a[j] + b[j], 0.f);
        partial += h * Wm2[j];
    }
    #pragma unroll
    for (int off = 16; off; off >>= 1)
        partial += __shfl_down_sync(0xffffffffu, partial, off);
    if (lane == 0) out[q] = fmaxf(partial + bm2[0], 0.f);
}

// ---------------------------------------------------------------------------
extern "C" void kernel_launch(void* const* d_in, const int* in_sizes, int n_in,
                              void* d_out, int out_size) {
    const float* x    = (const float*)d_in[0];
    const int*   ei   = (const int*)  d_in[1];
    const int*   qry  = (const int*)  d_in[2];
    const float* W1l  = (const float*)d_in[3];
    const float* b1l  = (const float*)d_in[4];
    const float* W1r  = (const float*)d_in[5];
    const float* b1r  = (const float*)d_in[6];
    const float* att1 = (const float*)d_in[7];
    const float* W2l  = (const float*)d_in[8];
    const float* b2l  = (const float*)d_in[9];
    const float* W2r  = (const float*)d_in[10];
    const float* b2r  = (const float*)d_in[11];
    const float* att2 = (const float*)d_in[12];
    const float* Wm1  = (const float*)d_in[13];
    const float* bm1  = (const float*)d_in[14];
    const float* Wm2  = (const float*)d_in[15];
    const float* bm2  = (const float*)d_in[16];
    float* out = (float*)d_out;

    const int N = in_sizes[0] / FIN;        // 50000
    const int E = in_sizes[1] / 2;          // 800000
    const int Q = in_sizes[2] / 2;          // 200000
    const int Etot = E + N;

    float *p_xl, *p_xr, *p_h, *p_emb;
    int *p_deg, *p_cursor, *p_rowptr, *p_colsrc;
    __nv_bfloat16 *p_ahi, *p_alo, *p_bthi, *p_btlo;
    cudaGetSymbolAddress((void**)&p_xl,     g_xl);
    cudaGetSymbolAddress((void**)&p_xr,     g_xr);
    cudaGetSymbolAddress((void**)&p_h,      g_h);
    cudaGetSymbolAddress((void**)&p_emb,    g_emb);
    cudaGetSymbolAddress((void**)&p_deg,    g_deg);
    cudaGetSymbolAddress((void**)&p_cursor, g_cursor);
    cudaGetSymbolAddress((void**)&p_rowptr, g_rowptr);
    cudaGetSymbolAddress((void**)&p_colsrc, g_colsrc);
    cudaGetSymbolAddress((void**)&p_ahi,    g_ahi);
    cudaGetSymbolAddress((void**)&p_alo,    g_alo);
    cudaGetSymbolAddress((void**)&p_bthi,   g_bthi);
    cudaGetSymbolAddress((void**)&p_btlo,   g_btlo);
    __nv_bfloat16* p_bthi2 = p_bthi + 256 * 256;
    __nv_bfloat16* p_btlo2 = p_btlo + 256 * 256;

    const int TPB = 256;
    int agg_blocks = (N * 32 + TPB - 1) / TPB;
    int wt_blocks = (256 * 256 + TPB - 1) / TPB;
    dim3 ggrid(2, (N + 127) / 128);   // 128 x 128 tiles over [N x 256]

    // ---------- Layer 1: convert + GEMMs (gemm at launch #4 for ncu) -------
    conv_act_kernel<<<2048, TPB>>>(x, FIN, FIN, FIN, N, p_ahi, p_alo);
    conv_wt_kernel<<<wt_blocks, TPB>>>(W1l, DDIM, FIN, DDIM, FIN, p_bthi, p_btlo);
    conv_wt_kernel<<<wt_blocks, TPB>>>(W1r, DDIM, FIN, DDIM, FIN, p_bthi2, p_btlo2);
    gemm_mma_kernel<<<ggrid, 256>>>(p_ahi, p_alo, FIN, p_bthi,  p_btlo,  b1l, p_xl, DPAD, N, DDIM);
    gemm_mma_kernel<<<ggrid, 256>>>(p_ahi, p_alo, FIN, p_bthi2, p_btlo2, b1r, p_xr, DPAD, N, DDIM);

    // ---------- CSR build ----------
    zero_deg_kernel<<<(N + TPB - 1) / TPB, TPB>>>(p_deg, N);
    hist_kernel<<<(Etot + TPB - 1) / TPB, TPB>>>(ei, p_deg, E, Etot);
    scan_kernel<<<1, 1024>>>(p_deg, p_rowptr, p_cursor, N);
    scatter_kernel<<<(Etot + TPB - 1) / TPB, TPB>>>(ei, p_cursor, p_colsrc, E, Etot);

    gat_agg_kernel<<<agg_blocks, TPB>>>(p_xl, p_xr, att1, p_rowptr, p_colsrc, p_h, N, 1);

    // ---------- Layer 2 ----------
    conv_act_kernel<<<2048, TPB>>>(p_h, DPAD, DDIM, DPAD, N, p_ahi, p_alo);
    conv_wt_kernel<<<wt_blocks, TPB>>>(W2l, DDIM, DDIM, DDIM, DPAD, p_bthi, p_btlo);
    conv_wt_kernel<<<wt_blocks, TPB>>>(W2r, DDIM, DDIM, DDIM, DPAD, p_bthi2, p_btlo2);
    gemm_mma_kernel<<<ggrid, 256>>>(p_ahi, p_alo, DPAD, p_bthi,  p_btlo,  b2l, p_xl, DPAD, N, DDIM);
    gemm_mma_kernel<<<ggrid, 256>>>(p_ahi, p_alo, DPAD, p_bthi2, p_btlo2, b2r, p_xr, DPAD, N, DDIM);

    gat_agg_kernel<<<agg_blocks, TPB>>>(p_xl, p_xr, att2, p_rowptr, p_colsrc, p_emb, N, 0);

    // ---------- Head: A = emb@Wm1_top + bm1 ; B = emb@Wm1_bot --------------
    conv_act_kernel<<<2048, TPB>>>(p_emb, DPAD, DDIM, DPAD, N, p_ahi, p_alo);
    conv_wt_kernel<<<wt_blocks, TPB>>>(Wm1,               HDIM, DDIM, HDIM, DPAD, p_bthi,  p_btlo);
    conv_wt_kernel<<<wt_blocks, TPB>>>(Wm1 + DDIM * HDIM, HDIM, DDIM, HDIM, DPAD, p_bthi2, p_btlo2);
    gemm_mma_kernel<<<ggrid, 256>>>(p_ahi, p_alo, DPAD, p_bthi,  p_btlo,  bm1,     p_xl, HDIM, N, HDIM);
    gemm_mma_kernel<<<ggrid, 256>>>(p_ahi, p_alo, DPAD, p_bthi2, p_btlo2, nullptr, p_xr, HDIM, N, HDIM);

    int q_blocks = (Q * 32 + TPB - 1) / TPB;
    head_kernel<<<q_blocks, TPB>>>(qry, p_xl, p_xr, Wm2, bm2, out, Q);
}

// round 7
// speedup vs baseline: 2.3747x; 1.4033x over previous
#include <cuda_runtime.h>
#include <cuda_bf16.h>
#include <stdint.h>
#include <math.h>
#include <float.h>

// Problem constants (shapes fixed by the dataset generator)
#define NNODES 50000
#define FIN    128
#define DDIM   250
#define DPAD   256
#define HDIM   256
#define EMAXT  850000   // E + N self loops

// ---------------- scratch (device globals; no runtime allocation) ----------
__device__ float g_xl [NNODES * DPAD];
__device__ float g_xr [NNODES * DPAD];
__device__ float g_h  [NNODES * DPAD];
__device__ float g_emb[NNODES * DPAD];
__device__ int   g_deg   [NNODES];
__device__ int   g_cursor[NNODES];
__device__ int   g_rowptr[NNODES + 1];
__device__ int   g_colsrc[EMAXT];
// split-bf16 buffers
__device__ __align__(16) __nv_bfloat16 g_ahi[NNODES * DPAD];
__device__ __align__(16) __nv_bfloat16 g_alo[NNODES * DPAD];
__device__ __align__(16) __nv_bfloat16 g_bthi[2][256 * 256];  // [n][k] transposed weights
__device__ __align__(16) __nv_bfloat16 g_btlo[2][256 * 256];

// ---------------- CSR build ------------------------------------------------
__global__ void zero_deg_kernel(int* deg, int n) {
    int i = blockIdx.x * blockDim.x + threadIdx.x;
    if (i < n) deg[i] = 0;
}

__global__ void hist_kernel(const int* __restrict__ ei, int* __restrict__ deg,
                            int E, int Etot) {
    int k = blockIdx.x * blockDim.x + threadIdx.x;
    if (k >= Etot) return;
    int dst = (k < E) ? ei[E + k] : (k - E);
    atomicAdd(&deg[dst], 1);
}

// single-block exclusive scan (shfl-based), chunked by 1024
__global__ void scan_kernel(const int* __restrict__ deg,
                            int* __restrict__ rowptr,
                            int* __restrict__ cursor, int n) {
    __shared__ int wpre[32];
    __shared__ int carry;
    int lane = threadIdx.x & 31, wid = threadIdx.x >> 5;
    if (threadIdx.x == 0) { carry = 0; rowptr[0] = 0; }
    __syncthreads();
    for (int base = 0; base < n; base += 1024) {
        int i = base + threadIdx.x;
        int v = (i < n) ? deg[i] : 0;
        int x = v;
        #pragma unroll
        for (int off = 1; off < 32; off <<= 1) {
            int t = __shfl_up_sync(0xffffffffu, x, off);
            if (lane >= off) x += t;
        }
        if (lane == 31) wpre[wid] = x;
        __syncthreads();
        if (wid == 0) {
            int y = wpre[lane];
            #pragma unroll
            for (int off = 1; off < 32; off <<= 1) {
                int t = __shfl_up_sync(0xffffffffu, y, off);
                if (lane >= off) y += t;
            }
            wpre[lane] = y;
        }
        __syncthreads();
        int warpoff = (wid == 0) ? 0 : wpre[wid - 1];
        int incl = x + warpoff + carry;
        if (i < n) { rowptr[i + 1] = incl; cursor[i] = incl - v; }
        __syncthreads();
        if (threadIdx.x == 1023) carry = incl;
        __syncthreads();
    }
}

__global__ void scatter_kernel(const int* __restrict__ ei,
                               int* __restrict__ cursor,
                               int* __restrict__ colsrc, int E, int Etot) {
    int k = blockIdx.x * blockDim.x + threadIdx.x;
    if (k >= Etot) return;
    int src, dst;
    if (k < E) { src = ei[k]; dst = ei[E + k]; }
    else       { src = k - E; dst = k - E; }
    int pos = atomicAdd(&cursor[dst], 1);
    colsrc[pos] = src;
}

// ---------------- split-bf16 conversions -----------------------------------
__global__ void conv_act_kernel(const float* __restrict__ A, int lda,
                                int Kreal, int Kpad, int M,
                                __nv_bfloat16* __restrict__ hi,
                                __nv_bfloat16* __restrict__ lo) {
    int idx = blockIdx.x * blockDim.x + threadIdx.x;
    int total = M * Kpad;
    int stride = gridDim.x * blockDim.x;
    for (; idx < total; idx += stride) {
        int row = idx / Kpad, k = idx - row * Kpad;
        float v = (k < Kreal) ? A[(size_t)row * lda + k] : 0.f;
        __nv_bfloat16 h = __float2bfloat16(v);
        float r = v - __bfloat162float(h);
        hi[idx] = h;
        lo[idx] = __float2bfloat16(r);
    }
}

// weights: fp32 W [K x Nreal] (row stride ldw) -> transposed hi/lo bf16 [256 x Kpad]
__global__ void conv_wt_kernel(const float* __restrict__ W, int ldw,
                               int Kreal, int Nreal, int Kpad,
                               __nv_bfloat16* __restrict__ hi,
                               __nv_bfloat16* __restrict__ lo) {
    int idx = blockIdx.x * blockDim.x + threadIdx.x;
    int total = 256 * Kpad;
    if (idx >= total) return;
    int n = idx / Kpad, k = idx - n * Kpad;
    float v = (n < Nreal && k < Kreal) ? W[(size_t)k * ldw + n] : 0.f;
    __nv_bfloat16 h = __float2bfloat16(v);
    float r = v - __bfloat162float(h);
    hi[idx] = h;
    lo[idx] = __float2bfloat16(r);
}

// ---------------- mma / ldmatrix / cp.async helpers ------------------------
__device__ __forceinline__ void mma16816(float* c, const unsigned* a,
                                         unsigned b0, unsigned b1) {
    asm volatile(
        "mma.sync.aligned.m16n8k16.row.col.f32.bf16.bf16.f32 "
        "{%0,%1,%2,%3},{%4,%5,%6,%7},{%8,%9},{%0,%1,%2,%3};"
        : "+f"(c[0]), "+f"(c[1]), "+f"(c[2]), "+f"(c[3])
        : "r"(a[0]), "r"(a[1]), "r"(a[2]), "r"(a[3]), "r"(b0), "r"(b1));
}

__device__ __forceinline__ void ldsm_x4(unsigned* r, unsigned addr) {
    asm volatile("ldmatrix.sync.aligned.m8n8.x4.shared.b16 {%0,%1,%2,%3}, [%4];"
                 : "=r"(r[0]), "=r"(r[1]), "=r"(r[2]), "=r"(r[3]) : "r"(addr));
}

__device__ __forceinline__ void cpasync16(unsigned saddr, const void* gaddr, int bytes) {
    asm volatile("cp.async.cg.shared.global [%0], [%1], 16, %2;"
                 :: "r"(saddr), "l"(gaddr), "r"(bytes));
}

// ---------------- split-bf16 tensor-core GEMM (cp.async double-buffered) ---
// C[M x Nreal] = A[M x K] * B[K x Nreal] (+bias); A as hi/lo bf16 [M x Kpad],
// B as transposed hi/lo bf16 [256 x Kpad]. Tile 128x128, 8 warps, 2 stages.
#define SROW 40                       // bf16 per smem row (32 k + 8 pad)
#define ARR_BYTES (128 * SROW * 2)    // 10240
#define STAGE_BYTES (4 * ARR_BYTES)   // 40960  (Ah, Al, Bh, Bl)
#define GEMM_SMEM (2 * STAGE_BYTES)   // 81920

extern __shared__ __align__(16) unsigned char g_dynsmem[];

__global__ void __launch_bounds__(256)
gemm_mma_kernel(const __nv_bfloat16* __restrict__ Ahi,
                const __nv_bfloat16* __restrict__ Alo, int Kpad,
                const __nv_bfloat16* __restrict__ BThi,
                const __nv_bfloat16* __restrict__ BTlo,
                const float* __restrict__ bias,
                float* __restrict__ C, int ldc, int M, int Nreal) {
    unsigned smem_u32 = (unsigned)__cvta_generic_to_shared(g_dynsmem);
    int tid = threadIdx.x;
    int lane = tid & 31, wid = tid >> 5;
    int g = lane >> 2, tk = lane & 3;
    int wm = (wid & 3) * 32;       // warp row offset in tile
    int wn = (wid >> 2) * 64;      // warp col offset in tile
    int row0 = blockIdx.y * 128;
    int col0 = blockIdx.x * 128;

    float acc[2][8][4];
    #pragma unroll
    for (int i = 0; i < 2; i++)
        #pragma unroll
        for (int j = 0; j < 8; j++)
            #pragma unroll
            for (int q = 0; q < 4; q++) acc[i][j][q] = 0.f;

    int nk = Kpad >> 5;

    // --- staging: 512 slots x 16B per array per stage ---
    auto stage_tiles = [&](int buf, int k0) {
        unsigned sb = smem_u32 + buf * STAGE_BYTES;
        #pragma unroll
        for (int it = 0; it < 2; it++) {
            int f = tid + it * 256;
            int r = f >> 2, kg = f & 3;
            unsigned soff = (unsigned)(r * SROW + kg * 8) * 2;
            int arow = row0 + r;
            int ab = (arow < M) ? 16 : 0;
            int arc = (arow < M) ? arow : 0;
            size_t ka = (size_t)arc * Kpad + k0 + kg * 8;
            cpasync16(sb + soff,                 Ahi + ka, ab);
            cpasync16(sb + ARR_BYTES + soff,     Alo + ka, ab);
            size_t kb = (size_t)(col0 + r) * Kpad + k0 + kg * 8;
            cpasync16(sb + 2 * ARR_BYTES + soff, BThi + kb, 16);
            cpasync16(sb + 3 * ARR_BYTES + soff, BTlo + kb, 16);
        }
    };

    stage_tiles(0, 0);
    asm volatile("cp.async.commit_group;");

    for (int i = 0; i < nk; i++) {
        if (i + 1 < nk) {
            stage_tiles((i + 1) & 1, (i + 1) * 32);
            asm volatile("cp.async.commit_group;");
            asm volatile("cp.async.wait_group 1;");
        } else {
            asm volatile("cp.async.wait_group 0;");
        }
        __syncthreads();

        unsigned sb = smem_u32 + (i & 1) * STAGE_BYTES;
        #pragma unroll
        for (int kk = 0; kk < 32; kk += 16) {
            unsigned ah[2][4], al[2][4];
            #pragma unroll
            for (int mf = 0; mf < 2; mf++) {
                int arow = wm + mf * 16 + (lane & 15);
                int acol = kk + ((lane >> 4) << 3);
                unsigned addr = sb + (unsigned)(arow * SROW + acol) * 2;
                ldsm_x4(ah[mf], addr);
                ldsm_x4(al[mf], addr + ARR_BYTES);
            }
            #pragma unroll
            for (int pr = 0; pr < 4; pr++) {      // pairs of n-fragments
                unsigned bh[4], bl[4];
                int brow = wn + pr * 16 + (lane & 7) + ((lane >> 4) << 3);
                int bcol = kk + (((lane >> 3) & 1) << 3);
                unsigned addr = sb + 2 * ARR_BYTES + (unsigned)(brow * SROW + bcol) * 2;
                ldsm_x4(bh, addr);
                ldsm_x4(bl, addr + ARR_BYTES);
                #pragma unroll
                for (int sub = 0; sub < 2; sub++) {
                    int nf = pr * 2 + sub;
                    unsigned b0h = bh[sub * 2], b1h = bh[sub * 2 + 1];
                    unsigned b0l = bl[sub * 2], b1l = bl[sub * 2 + 1];
                    #pragma unroll
                    for (int mf = 0; mf < 2; mf++) {
                        mma16816(acc[mf][nf], ah[mf], b0h, b1h);  // hi*hi
                        mma16816(acc[mf][nf], al[mf], b0h, b1h);  // lo*hi
                        mma16816(acc[mf][nf], ah[mf], b0l, b1l);  // hi*lo
                    }
                }
            }
        }
        __syncthreads();
    }

    // epilogue
    #pragma unroll
    for (int mf = 0; mf < 2; mf++) {
        #pragma unroll
        for (int nf = 0; nf < 8; nf++) {
            int col = col0 + wn + nf * 8 + 2 * tk;
            if (col >= Nreal) continue;          // cols even, Nreal even -> col+1 valid
            float bv0 = bias ? bias[col]     : 0.f;
            float bv1 = bias ? bias[col + 1] : 0.f;
            int r = row0 + wm + mf * 16 + g;
            if (r < M) {
                float2 v = make_float2(acc[mf][nf][0] + bv0, acc[mf][nf][1] + bv1);
                *(float2*)&C[(size_t)r * ldc + col] = v;
            }
            int r2 = r + 8;
            if (r2 < M) {
                float2 v = make_float2(acc[mf][nf][2] + bv0, acc[mf][nf][3] + bv1);
                *(float2*)&C[(size_t)r2 * ldc + col] = v;
            }
        }
    }
}

// ---------------- fused GATv2 softmax-aggregate: one warp per dst node ------
__global__ void gat_agg_kernel(const float* __restrict__ xl,
                               const float* __restrict__ xr,
                               const float* __restrict__ att,
                               const int* __restrict__ rowptr,
                               const int* __restrict__ colsrc,
                               float* __restrict__ outp,
                               int n, int do_relu) {
    int w = (blockIdx.x * blockDim.x + threadIdx.x) >> 5;
    if (w >= n) return;
    int lane = threadIdx.x & 31;

    float attv[8], xrv[8], acc[8];
    #pragma unroll
    for (int j = 0; j < 8; j++) {
        int d = j * 32 + lane;
        bool ok = d < DDIM;
        attv[j] = ok ? att[d] : 0.f;
        xrv[j]  = ok ? xr[(size_t)w * DPAD + d] : 0.f;
        acc[j] = 0.f;
    }
    float m = -FLT_MAX, s = 0.f;
    int beg = rowptr[w], end = rowptr[w + 1];
    for (int p = beg; p < end; p++) {
        int src = colsrc[p];
        const float* xs = xl + (size_t)src * DPAD;
        float xv[8];
        float part = 0.f;
        #pragma unroll
        for (int j = 0; j < 8; j++) {
            int d = j * 32 + lane;
            float v = (d < DDIM) ? xs[d] : 0.f;
            xv[j] = v;
            float hsum = v + xrv[j];
            float lr = hsum > 0.f ? hsum : 0.2f * hsum;
            part += attv[j] * lr;
        }
        #pragma unroll
        for (int off = 16; off; off >>= 1)
            part += __shfl_xor_sync(0xffffffffu, part, off);
        float mn = fmaxf(m, part);
        float c   = __expf(m - mn);
        float wgt = __expf(part - mn);
        s = s * c + wgt;
        #pragma unroll
        for (int j = 0; j < 8; j++) acc[j] = acc[j] * c + wgt * xv[j];
        m = mn;
    }
    float inv = 1.f / s;
    #pragma unroll
    for (int j = 0; j < 8; j++) {
        int d = j * 32 + lane;
        if (d < DDIM) {
            float v = acc[j] * inv;
            if (do_relu) v = fmaxf(v, 0.f);
            outp[(size_t)w * DPAD + d] = v;
        }
    }
}

// ---------------- head: out[q] = relu(dot(relu(A[q0]+B[q1]), Wm2)+bm2) -----
__global__ void head_kernel(const int* __restrict__ query,
                            const float* __restrict__ Atab,
                            const float* __restrict__ Btab,
                            const float* __restrict__ Wm2,
                            const float* __restrict__ bm2,
                            float* __restrict__ out, int Q) {
    int q = (blockIdx.x * blockDim.x + threadIdx.x) >> 5;
    if (q >= Q) return;
    int lane = threadIdx.x & 31;
    int q0 = query[2 * q], q1 = query[2 * q + 1];
    const float* a = Atab + (size_t)q0 * HDIM;
    const float* b = Btab + (size_t)q1 * HDIM;
    float partial = 0.f;
    #pragma unroll
    for (int j = lane; j < HDIM; j += 32) {
        float h = fmaxf(a[j] + b[j], 0.f);
        partial += h * Wm2[j];
    }
    #pragma unroll
    for (int off = 16; off; off >>= 1)
        partial += __shfl_down_sync(0xffffffffu, partial, off);
    if (lane == 0) out[q] = fmaxf(partial + bm2[0], 0.f);
}

// ---------------------------------------------------------------------------
extern "C" void kernel_launch(void* const* d_in, const int* in_sizes, int n_in,
                              void* d_out, int out_size) {
    const float* x    = (const float*)d_in[0];
    const int*   ei   = (const int*)  d_in[1];
    const int*   qry  = (const int*)  d_in[2];
    const float* W1l  = (const float*)d_in[3];
    const float* b1l  = (const float*)d_in[4];
    const float* W1r  = (const float*)d_in[5];
    const float* b1r  = (const float*)d_in[6];
    const float* att1 = (const float*)d_in[7];
    const float* W2l  = (const float*)d_in[8];
    const float* b2l  = (const float*)d_in[9];
    const float* W2r  = (const float*)d_in[10];
    const float* b2r  = (const float*)d_in[11];
    const float* att2 = (const float*)d_in[12];
    const float* Wm1  = (const float*)d_in[13];
    const float* bm1  = (const float*)d_in[14];
    const float* Wm2  = (const float*)d_in[15];
    const float* bm2  = (const float*)d_in[16];
    float* out = (float*)d_out;

    const int N = in_sizes[0] / FIN;        // 50000
    const int E = in_sizes[1] / 2;          // 800000
    const int Q = in_sizes[2] / 2;          // 200000
    const int Etot = E + N;

    float *p_xl, *p_xr, *p_h, *p_emb;
    int *p_deg, *p_cursor, *p_rowptr, *p_colsrc;
    __nv_bfloat16 *p_ahi, *p_alo, *p_bthi, *p_btlo;
    cudaGetSymbolAddress((void**)&p_xl,     g_xl);
    cudaGetSymbolAddress((void**)&p_xr,     g_xr);
    cudaGetSymbolAddress((void**)&p_h,      g_h);
    cudaGetSymbolAddress((void**)&p_emb,    g_emb);
    cudaGetSymbolAddress((void**)&p_deg,    g_deg);
    cudaGetSymbolAddress((void**)&p_cursor, g_cursor);
    cudaGetSymbolAddress((void**)&p_rowptr, g_rowptr);
    cudaGetSymbolAddress((void**)&p_colsrc, g_colsrc);
    cudaGetSymbolAddress((void**)&p_ahi,    g_ahi);
    cudaGetSymbolAddress((void**)&p_alo,    g_alo);
    cudaGetSymbolAddress((void**)&p_bthi,   g_bthi);
    cudaGetSymbolAddress((void**)&p_btlo,   g_btlo);
    __nv_bfloat16* p_bthi2 = p_bthi + 256 * 256;
    __nv_bfloat16* p_btlo2 = p_btlo + 256 * 256;

    cudaFuncSetAttribute(gemm_mma_kernel,
                         cudaFuncAttributeMaxDynamicSharedMemorySize, GEMM_SMEM);

    const int TPB = 256;
    int agg_blocks = (N * 32 + TPB - 1) / TPB;
    int wt_blocks = (256 * 256 + TPB - 1) / TPB;
    dim3 ggrid(2, (N + 127) / 128);   // 128 x 128 tiles over [N x 256]

    // ---------- Layer 1: convert + GEMMs (gemm at launch #4 for ncu) -------
    conv_act_kernel<<<2048, TPB>>>(x, FIN, FIN, FIN, N, p_ahi, p_alo);
    conv_wt_kernel<<<wt_blocks, TPB>>>(W1l, DDIM, FIN, DDIM, FIN, p_bthi, p_btlo);
    conv_wt_kernel<<<wt_blocks, TPB>>>(W1r, DDIM, FIN, DDIM, FIN, p_bthi2, p_btlo2);
    gemm_mma_kernel<<<ggrid, 256, GEMM_SMEM>>>(p_ahi, p_alo, FIN, p_bthi,  p_btlo,  b1l, p_xl, DPAD, N, DDIM);
    gemm_mma_kernel<<<ggrid, 256, GEMM_SMEM>>>(p_ahi, p_alo, FIN, p_bthi2, p_btlo2, b1r, p_xr, DPAD, N, DDIM);

    // ---------- CSR build ----------
    zero_deg_kernel<<<(N + TPB - 1) / TPB, TPB>>>(p_deg, N);
    hist_kernel<<<(Etot + TPB - 1) / TPB, TPB>>>(ei, p_deg, E, Etot);
    scan_kernel<<<1, 1024>>>(p_deg, p_rowptr, p_cursor, N);
    scatter_kernel<<<(Etot + TPB - 1) / TPB, TPB>>>(ei, p_cursor, p_colsrc, E, Etot);

    gat_agg_kernel<<<agg_blocks, TPB>>>(p_xl, p_xr, att1, p_rowptr, p_colsrc, p_h, N, 1);

    // ---------- Layer 2 ----------
    conv_act_kernel<<<2048, TPB>>>(p_h, DPAD, DDIM, DPAD, N, p_ahi, p_alo);
    conv_wt_kernel<<<wt_blocks, TPB>>>(W2l, DDIM, DDIM, DDIM, DPAD, p_bthi, p_btlo);
    conv_wt_kernel<<<wt_blocks, TPB>>>(W2r, DDIM, DDIM, DDIM, DPAD, p_bthi2, p_btlo2);
    gemm_mma_kernel<<<ggrid, 256, GEMM_SMEM>>>(p_ahi, p_alo, DPAD, p_bthi,  p_btlo,  b2l, p_xl, DPAD, N, DDIM);
    gemm_mma_kernel<<<ggrid, 256, GEMM_SMEM>>>(p_ahi, p_alo, DPAD, p_bthi2, p_btlo2, b2r, p_xr, DPAD, N, DDIM);

    gat_agg_kernel<<<agg_blocks, TPB>>>(p_xl, p_xr, att2, p_rowptr, p_colsrc, p_emb, N, 0);

    // ---------- Head: A = emb@Wm1_top + bm1 ; B = emb@Wm1_bot --------------
    conv_act_kernel<<<2048, TPB>>>(p_emb, DPAD, DDIM, DPAD, N, p_ahi, p_alo);
    conv_wt_kernel<<<wt_blocks, TPB>>>(Wm1,               HDIM, DDIM, HDIM, DPAD, p_bthi,  p_btlo);
    conv_wt_kernel<<<wt_blocks, TPB>>>(Wm1 + DDIM * HDIM, HDIM, DDIM, HDIM, DPAD, p_bthi2, p_btlo2);
    gemm_mma_kernel<<<ggrid, 256, GEMM_SMEM>>>(p_ahi, p_alo, DPAD, p_bthi,  p_btlo,  bm1,     p_xl, HDIM, N, HDIM);
    gemm_mma_kernel<<<ggrid, 256, GEMM_SMEM>>>(p_ahi, p_alo, DPAD, p_bthi2, p_btlo2, nullptr, p_xr, HDIM, N, HDIM);

    int q_blocks = (Q * 32 + TPB - 1) / TPB;
    head_kernel<<<q_blocks, TPB>>>(qry, p_xl, p_xr, Wm2, bm2, out, Q);
}

// round 8
// speedup vs baseline: 2.8694x; 1.2083x over previous
#include <cuda_runtime.h>
#include <cuda_bf16.h>
#include <stdint.h>
#include <math.h>
#include <float.h>

// Problem constants (shapes fixed by the dataset generator)
#define NNODES 50000
#define FIN    128
#define DDIM   250
#define DPAD   256
#define HDIM   256
#define EMAXT  850000   // E + N self loops

// ---------------- scratch (device globals; no runtime allocation) ----------
__device__ float g_xl [NNODES * DPAD];
__device__ float g_xr [NNODES * DPAD];
__device__ int   g_deg   [NNODES];
__device__ int   g_cursor[NNODES];
__device__ int   g_rowptr[NNODES + 1];
__device__ int   g_colsrc[EMAXT];
// split-bf16 buffers
__device__ __align__(16) __nv_bfloat16 g_ahi[NNODES * DPAD];
__device__ __align__(16) __nv_bfloat16 g_alo[NNODES * DPAD];
__device__ __align__(16) __nv_bfloat16 g_bthi[2][256 * 256];  // [n][k] transposed weights
__device__ __align__(16) __nv_bfloat16 g_btlo[2][256 * 256];

// ---------------- CSR build ------------------------------------------------
__global__ void zero_deg_kernel(int* deg, int n) {
    int i = blockIdx.x * blockDim.x + threadIdx.x;
    if (i < n) deg[i] = 0;
}

__global__ void hist_kernel(const int* __restrict__ ei, int* __restrict__ deg,
                            int E, int Etot) {
    int k = blockIdx.x * blockDim.x + threadIdx.x;
    if (k >= Etot) return;
    int dst = (k < E) ? ei[E + k] : (k - E);
    atomicAdd(&deg[dst], 1);
}

// single-block exclusive scan (shfl-based), chunked by 1024
__global__ void scan_kernel(const int* __restrict__ deg,
                            int* __restrict__ rowptr,
                            int* __restrict__ cursor, int n) {
    __shared__ int wpre[32];
    __shared__ int carry;
    int lane = threadIdx.x & 31, wid = threadIdx.x >> 5;
    if (threadIdx.x == 0) { carry = 0; rowptr[0] = 0; }
    __syncthreads();
    for (int base = 0; base < n; base += 1024) {
        int i = base + threadIdx.x;
        int v = (i < n) ? deg[i] : 0;
        int x = v;
        #pragma unroll
        for (int off = 1; off < 32; off <<= 1) {
            int t = __shfl_up_sync(0xffffffffu, x, off);
            if (lane >= off) x += t;
        }
        if (lane == 31) wpre[wid] = x;
        __syncthreads();
        if (wid == 0) {
            int y = wpre[lane];
            #pragma unroll
            for (int off = 1; off < 32; off <<= 1) {
                int t = __shfl_up_sync(0xffffffffu, y, off);
                if (lane >= off) y += t;
            }
            wpre[lane] = y;
        }
        __syncthreads();
        int warpoff = (wid == 0) ? 0 : wpre[wid - 1];
        int incl = x + warpoff + carry;
        if (i < n) { rowptr[i + 1] = incl; cursor[i] = incl - v; }
        __syncthreads();
        if (threadIdx.x == 1023) carry = incl;
        __syncthreads();
    }
}

__global__ void scatter_kernel(const int* __restrict__ ei,
                               int* __restrict__ cursor,
                               int* __restrict__ colsrc, int E, int Etot) {
    int k = blockIdx.x * blockDim.x + threadIdx.x;
    if (k >= Etot) return;
    int src, dst;
    if (k < E) { src = ei[k]; dst = ei[E + k]; }
    else       { src = k - E; dst = k - E; }
    int pos = atomicAdd(&cursor[dst], 1);
    colsrc[pos] = src;
}

// ---------------- split-bf16 conversions -----------------------------------
__global__ void conv_act_kernel(const float* __restrict__ A, int lda,
                                int Kreal, int Kpad, int M,
                                __nv_bfloat16* __restrict__ hi,
                                __nv_bfloat16* __restrict__ lo) {
    int idx = blockIdx.x * blockDim.x + threadIdx.x;
    int total = M * Kpad;
    int stride = gridDim.x * blockDim.x;
    for (; idx < total; idx += stride) {
        int row = idx / Kpad, k = idx - row * Kpad;
        float v = (k < Kreal) ? A[(size_t)row * lda + k] : 0.f;
        __nv_bfloat16 h = __float2bfloat16(v);
        float r = v - __bfloat162float(h);
        hi[idx] = h;
        lo[idx] = __float2bfloat16(r);
    }
}

// weights: fp32 W [K x Nreal] (row stride ldw) -> transposed hi/lo bf16 [256 x Kpad]
__global__ void conv_wt_kernel(const float* __restrict__ W, int ldw,
                               int Kreal, int Nreal, int Kpad,
                               __nv_bfloat16* __restrict__ hi,
                               __nv_bfloat16* __restrict__ lo) {
    int idx = blockIdx.x * blockDim.x + threadIdx.x;
    int total = 256 * Kpad;
    if (idx >= total) return;
    int n = idx / Kpad, k = idx - n * Kpad;
    float v = (n < Nreal && k < Kreal) ? W[(size_t)k * ldw + n] : 0.f;
    __nv_bfloat16 h = __float2bfloat16(v);
    float r = v - __bfloat162float(h);
    hi[idx] = h;
    lo[idx] = __float2bfloat16(r);
}

// ---------------- mma / ldmatrix / cp.async helpers ------------------------
__device__ __forceinline__ void mma16816(float* c, const unsigned* a,
                                         unsigned b0, unsigned b1) {
    asm volatile(
        "mma.sync.aligned.m16n8k16.row.col.f32.bf16.bf16.f32 "
        "{%0,%1,%2,%3},{%4,%5,%6,%7},{%8,%9},{%0,%1,%2,%3};"
        : "+f"(c[0]), "+f"(c[1]), "+f"(c[2]), "+f"(c[3])
        : "r"(a[0]), "r"(a[1]), "r"(a[2]), "r"(a[3]), "r"(b0), "r"(b1));
}

__device__ __forceinline__ void ldsm_x4(unsigned* r, unsigned addr) {
    asm volatile("ldmatrix.sync.aligned.m8n8.x4.shared.b16 {%0,%1,%2,%3}, [%4];"
                 : "=r"(r[0]), "=r"(r[1]), "=r"(r[2]), "=r"(r[3]) : "r"(addr));
}

__device__ __forceinline__ void cpasync16(unsigned saddr, const void* gaddr, int bytes) {
    asm volatile("cp.async.cg.shared.global [%0], [%1], 16, %2;"
                 :: "r"(saddr), "l"(gaddr), "r"(bytes));
}

// ---------------- split-bf16 tensor-core GEMM (cp.async double-buffered) ---
// C[M x Nreal] = A[M x K] * B[K x Nreal] (+bias); A as hi/lo bf16 [M x Kpad],
// B as transposed hi/lo bf16 [256 x Kpad]. Tile 128x128, 8 warps, 2 stages.
#define SROW 40                       // bf16 per smem row (32 k + 8 pad)
#define ARR_BYTES (128 * SROW * 2)    // 10240
#define STAGE_BYTES (4 * ARR_BYTES)   // 40960  (Ah, Al, Bh, Bl)
#define GEMM_SMEM (2 * STAGE_BYTES)   // 81920

extern __shared__ __align__(16) unsigned char g_dynsmem[];

__global__ void __launch_bounds__(256, 2)
gemm_mma_kernel(const __nv_bfloat16* __restrict__ Ahi,
                const __nv_bfloat16* __restrict__ Alo, int Kpad,
                const __nv_bfloat16* __restrict__ BThi,
                const __nv_bfloat16* __restrict__ BTlo,
                const float* __restrict__ bias,
                float* __restrict__ C, int ldc, int M, int Nreal) {
    unsigned smem_u32 = (unsigned)__cvta_generic_to_shared(g_dynsmem);
    int tid = threadIdx.x;
    int lane = tid & 31, wid = tid >> 5;
    int g = lane >> 2, tk = lane & 3;
    int wm = (wid & 3) * 32;       // warp row offset in tile
    int wn = (wid >> 2) * 64;      // warp col offset in tile
    int row0 = blockIdx.y * 128;
    int col0 = blockIdx.x * 128;

    float acc[2][8][4];
    #pragma unroll
    for (int i = 0; i < 2; i++)
        #pragma unroll
        for (int j = 0; j < 8; j++)
            #pragma unroll
            for (int q = 0; q < 4; q++) acc[i][j][q] = 0.f;

    int nk = Kpad >> 5;

    // --- staging: 512 slots x 16B per array per stage ---
    auto stage_tiles = [&](int buf, int k0) {
        unsigned sb = smem_u32 + buf * STAGE_BYTES;
        #pragma unroll
        for (int it = 0; it < 2; it++) {
            int f = tid + it * 256;
            int r = f >> 2, kg = f & 3;
            unsigned soff = (unsigned)(r * SROW + kg * 8) * 2;
            int arow = row0 + r;
            int ab = (arow < M) ? 16 : 0;
            int arc = (arow < M) ? arow : 0;
            size_t ka = (size_t)arc * Kpad + k0 + kg * 8;
            cpasync16(sb + soff,                 Ahi + ka, ab);
            cpasync16(sb + ARR_BYTES + soff,     Alo + ka, ab);
            size_t kb = (size_t)(col0 + r) * Kpad + k0 + kg * 8;
            cpasync16(sb + 2 * ARR_BYTES + soff, BThi + kb, 16);
            cpasync16(sb + 3 * ARR_BYTES + soff, BTlo + kb, 16);
        }
    };

    stage_tiles(0, 0);
    asm volatile("cp.async.commit_group;");

    for (int i = 0; i < nk; i++) {
        if (i + 1 < nk) {
            stage_tiles((i + 1) & 1, (i + 1) * 32);
            asm volatile("cp.async.commit_group;");
            asm volatile("cp.async.wait_group 1;");
        } else {
            asm volatile("cp.async.wait_group 0;");
        }
        __syncthreads();

        unsigned sb = smem_u32 + (i & 1) * STAGE_BYTES;
        #pragma unroll
        for (int kk = 0; kk < 32; kk += 16) {
            unsigned ah[2][4], al[2][4];
            #pragma unroll
            for (int mf = 0; mf < 2; mf++) {
                int arow = wm + mf * 16 + (lane & 15);
                int acol = kk + ((lane >> 4) << 3);
                unsigned addr = sb + (unsigned)(arow * SROW + acol) * 2;
                ldsm_x4(ah[mf], addr);
                ldsm_x4(al[mf], addr + ARR_BYTES);
            }
            #pragma unroll
            for (int pr = 0; pr < 4; pr++) {      // pairs of n-fragments
                unsigned bh[4], bl[4];
                int brow = wn + pr * 16 + (lane & 7) + ((lane >> 4) << 3);
                int bcol = kk + (((lane >> 3) & 1) << 3);
                unsigned addr = sb + 2 * ARR_BYTES + (unsigned)(brow * SROW + bcol) * 2;
                ldsm_x4(bh, addr);
                ldsm_x4(bl, addr + ARR_BYTES);
                #pragma unroll
                for (int sub = 0; sub < 2; sub++) {
                    int nf = pr * 2 + sub;
                    unsigned b0h = bh[sub * 2], b1h = bh[sub * 2 + 1];
                    unsigned b0l = bl[sub * 2], b1l = bl[sub * 2 + 1];
                    #pragma unroll
                    for (int mf = 0; mf < 2; mf++) {
                        mma16816(acc[mf][nf], ah[mf], b0h, b1h);  // hi*hi
                        mma16816(acc[mf][nf], al[mf], b0h, b1h);  // lo*hi
                        mma16816(acc[mf][nf], ah[mf], b0l, b1l);  // hi*lo
                    }
                }
            }
        }
        __syncthreads();
    }

    // epilogue
    #pragma unroll
    for (int mf = 0; mf < 2; mf++) {
        #pragma unroll
        for (int nf = 0; nf < 8; nf++) {
            int col = col0 + wn + nf * 8 + 2 * tk;
            if (col >= Nreal) continue;          // cols even, Nreal even -> col+1 valid
            float bv0 = bias ? bias[col]     : 0.f;
            float bv1 = bias ? bias[col + 1] : 0.f;
            int r = row0 + wm + mf * 16 + g;
            if (r < M) {
                float2 v = make_float2(acc[mf][nf][0] + bv0, acc[mf][nf][1] + bv1);
                *(float2*)&C[(size_t)r * ldc + col] = v;
            }
            int r2 = r + 8;
            if (r2 < M) {
                float2 v = make_float2(acc[mf][nf][2] + bv0, acc[mf][nf][3] + bv1);
                *(float2*)&C[(size_t)r2 * ldc + col] = v;
            }
        }
    }
}

// ---------------- fused GATv2 softmax-aggregate (writes split-bf16) --------
// one warp per dst node; online softmax over CSR; output straight into the
// next GEMM's A operand (hi/lo bf16, DPAD wide, zero padded).
__global__ void gat_agg_kernel(const float* __restrict__ xl,
                               const float* __restrict__ xr,
                               const float* __restrict__ att,
                               const int* __restrict__ rowptr,
                               const int* __restrict__ colsrc,
                               __nv_bfloat16* __restrict__ ohi,
                               __nv_bfloat16* __restrict__ olo,
                               int n, int do_relu) {
    int w = (blockIdx.x * blockDim.x + threadIdx.x) >> 5;
    if (w >= n) return;
    int lane = threadIdx.x & 31;

    float attv[8], xrv[8], acc[8];
    #pragma unroll
    for (int j = 0; j < 8; j++) {
        int d = j * 32 + lane;
        bool ok = d < DDIM;
        attv[j] = ok ? att[d] : 0.f;
        xrv[j]  = ok ? xr[(size_t)w * DPAD + d] : 0.f;
        acc[j] = 0.f;
    }
    float m = -FLT_MAX, s = 0.f;
    int beg = rowptr[w], end = rowptr[w + 1];
    for (int p = beg; p < end; p++) {
        int src = colsrc[p];
        const float* xs = xl + (size_t)src * DPAD;
        float xv[8];
        float part = 0.f;
        #pragma unroll
        for (int j = 0; j < 8; j++) {
            int d = j * 32 + lane;
            float v = (d < DDIM) ? xs[d] : 0.f;
            xv[j] = v;
            float hsum = v + xrv[j];
            float lr = hsum > 0.f ? hsum : 0.2f * hsum;
            part += attv[j] * lr;
        }
        #pragma unroll
        for (int off = 16; off; off >>= 1)
            part += __shfl_xor_sync(0xffffffffu, part, off);
        float mn = fmaxf(m, part);
        float c   = __expf(m - mn);
        float wgt = __expf(part - mn);
        s = s * c + wgt;
        #pragma unroll
        for (int j = 0; j < 8; j++) acc[j] = acc[j] * c + wgt * xv[j];
        m = mn;
    }
    float inv = 1.f / s;
    #pragma unroll
    for (int j = 0; j < 8; j++) {
        int d = j * 32 + lane;
        float v = acc[j] * inv;
        if (do_relu) v = fmaxf(v, 0.f);
        if (d >= DDIM) v = 0.f;
        __nv_bfloat16 hb = __float2bfloat16(v);
        float r = v - __bfloat162float(hb);
        size_t o = (size_t)w * DPAD + d;
        ohi[o] = hb;
        olo[o] = __float2bfloat16(r);
    }
}

// ---------------- head: out[q] = relu(dot(relu(A[q0]+B[q1]), Wm2)+bm2) -----
__global__ void head_kernel(const int* __restrict__ query,
                            const float* __restrict__ Atab,
                            const float* __restrict__ Btab,
                            const float* __restrict__ Wm2,
                            const float* __restrict__ bm2,
                            float* __restrict__ out, int Q) {
    int q = (blockIdx.x * blockDim.x + threadIdx.x) >> 5;
    if (q >= Q) return;
    int lane = threadIdx.x & 31;
    int q0 = query[2 * q], q1 = query[2 * q + 1];
    const float* a = Atab + (size_t)q0 * HDIM;
    const float* b = Btab + (size_t)q1 * HDIM;
    float partial = 0.f;
    #pragma unroll
    for (int j = lane; j < HDIM; j += 32) {
        float h = fmaxf(a[j] + b[j], 0.f);
        partial += h * Wm2[j];
    }
    #pragma unroll
    for (int off = 16; off; off >>= 1)
        partial += __shfl_down_sync(0xffffffffu, partial, off);
    if (lane == 0) out[q] = fmaxf(partial + bm2[0], 0.f);
}

// ---------------------------------------------------------------------------
extern "C" void kernel_launch(void* const* d_in, const int* in_sizes, int n_in,
                              void* d_out, int out_size) {
    const float* x    = (const float*)d_in[0];
    const int*   ei   = (const int*)  d_in[1];
    const int*   qry  = (const int*)  d_in[2];
    const float* W1l  = (const float*)d_in[3];
    const float* b1l  = (const float*)d_in[4];
    const float* W1r  = (const float*)d_in[5];
    const float* b1r  = (const float*)d_in[6];
    const float* att1 = (const float*)d_in[7];
    const float* W2l  = (const float*)d_in[8];
    const float* b2l  = (const float*)d_in[9];
    const float* W2r  = (const float*)d_in[10];
    const float* b2r  = (const float*)d_in[11];
    const float* att2 = (const float*)d_in[12];
    const float* Wm1  = (const float*)d_in[13];
    const float* bm1  = (const float*)d_in[14];
    const float* Wm2  = (const float*)d_in[15];
    const float* bm2  = (const float*)d_in[16];
    float* out = (float*)d_out;

    const int N = in_sizes[0] / FIN;        // 50000
    const int E = in_sizes[1] / 2;          // 800000
    const int Q = in_sizes[2] / 2;          // 200000
    const int Etot = E + N;

    float *p_xl, *p_xr;
    int *p_deg, *p_cursor, *p_rowptr, *p_colsrc;
    __nv_bfloat16 *p_ahi, *p_alo, *p_bthi, *p_btlo;
    cudaGetSymbolAddress((void**)&p_xl,     g_xl);
    cudaGetSymbolAddress((void**)&p_xr,     g_xr);
    cudaGetSymbolAddress((void**)&p_deg,    g_deg);
    cudaGetSymbolAddress((void**)&p_cursor, g_cursor);
    cudaGetSymbolAddress((void**)&p_rowptr, g_rowptr);
    cudaGetSymbolAddress((void**)&p_colsrc, g_colsrc);
    cudaGetSymbolAddress((void**)&p_ahi,    g_ahi);
    cudaGetSymbolAddress((void**)&p_alo,    g_alo);
    cudaGetSymbolAddress((void**)&p_bthi,   g_bthi);
    cudaGetSymbolAddress((void**)&p_btlo,   g_btlo);
    __nv_bfloat16* p_bthi2 = p_bthi + 256 * 256;
    __nv_bfloat16* p_btlo2 = p_btlo + 256 * 256;

    cudaFuncSetAttribute(gemm_mma_kernel,
                         cudaFuncAttributeMaxDynamicSharedMemorySize, GEMM_SMEM);

    const int TPB = 256;
    int agg_blocks = (N * 32 + TPB - 1) / TPB;
    int wt_blocks = (256 * 256 + TPB - 1) / TPB;
    dim3 ggrid(2, (N + 127) / 128);   // 128 x 128 tiles over [N x 256]

    // ---------- Layer 1: convert + GEMMs (gemm at launch #4 for ncu) -------
    conv_act_kernel<<<2048, TPB>>>(x, FIN, FIN, FIN, N, p_ahi, p_alo);
    conv_wt_kernel<<<wt_blocks, TPB>>>(W1l, DDIM, FIN, DDIM, FIN, p_bthi, p_btlo);
    conv_wt_kernel<<<wt_blocks, TPB>>>(W1r, DDIM, FIN, DDIM, FIN, p_bthi2, p_btlo2);
    gemm_mma_kernel<<<ggrid, 256, GEMM_SMEM>>>(p_ahi, p_alo, FIN, p_bthi,  p_btlo,  b1l, p_xl, DPAD, N, DDIM);
    gemm_mma_kernel<<<ggrid, 256, GEMM_SMEM>>>(p_ahi, p_alo, FIN, p_bthi2, p_btlo2, b1r, p_xr, DPAD, N, DDIM);

    // ---------- CSR build ----------
    zero_deg_kernel<<<(N + TPB - 1) / TPB, TPB>>>(p_deg, N);
    hist_kernel<<<(Etot + TPB - 1) / TPB, TPB>>>(ei, p_deg, E, Etot);
    scan_kernel<<<1, 1024>>>(p_deg, p_rowptr, p_cursor, N);
    scatter_kernel<<<(Etot + TPB - 1) / TPB, TPB>>>(ei, p_cursor, p_colsrc, E, Etot);

    // agg1: write h directly as split-bf16 A operand of layer 2
    gat_agg_kernel<<<agg_blocks, TPB>>>(p_xl, p_xr, att1, p_rowptr, p_colsrc,
                                        p_ahi, p_alo, N, 1);

    // ---------- Layer 2 ----------
    conv_wt_kernel<<<wt_blocks, TPB>>>(W2l, DDIM, DDIM, DDIM, DPAD, p_bthi, p_btlo);
    conv_wt_kernel<<<wt_blocks, TPB>>>(W2r, DDIM, DDIM, DDIM, DPAD, p_bthi2, p_btlo2);
    gemm_mma_kernel<<<ggrid, 256, GEMM_SMEM>>>(p_ahi, p_alo, DPAD, p_bthi,  p_btlo,  b2l, p_xl, DPAD, N, DDIM);
    gemm_mma_kernel<<<ggrid, 256, GEMM_SMEM>>>(p_ahi, p_alo, DPAD, p_bthi2, p_btlo2, b2r, p_xr, DPAD, N, DDIM);

    // agg2: write emb directly as split-bf16 A operand of the head GEMMs
    gat_agg_kernel<<<agg_blocks, TPB>>>(p_xl, p_xr, att2, p_rowptr, p_colsrc,
                                        p_ahi, p_alo, N, 0);

    // ---------- Head: A = emb@Wm1_top + bm1 ; B = emb@Wm1_bot --------------
    conv_wt_kernel<<<wt_blocks, TPB>>>(Wm1,               HDIM, DDIM, HDIM, DPAD, p_bthi,  p_btlo);
    conv_wt_kernel<<<wt_blocks, TPB>>>(Wm1 + DDIM * HDIM, HDIM, DDIM, HDIM, DPAD, p_bthi2, p_btlo2);
    gemm_mma_kernel<<<ggrid, 256, GEMM_SMEM>>>(p_ahi, p_alo, DPAD, p_bthi,  p_btlo,  bm1,     p_xl, HDIM, N, HDIM);
    gemm_mma_kernel<<<ggrid, 256, GEMM_SMEM>>>(p_ahi, p_alo, DPAD, p_bthi2, p_btlo2, nullptr, p_xr, HDIM, N, HDIM);

    int q_blocks = (Q * 32 + TPB - 1) / TPB;
    head_kernel<<<q_blocks, TPB>>>(qry, p_xl, p_xr, Wm2, bm2, out, Q);
}